// round 1
// baseline (speedup 1.0000x reference)
#include <cuda_runtime.h>
#include <math.h>

#define VV      200000
#define EE      128
#define PAD_ID  199999
#define KK      32            // KNN_K
#define BQ      2048
#define BS      5
#define NN      128
#define KT      64
#define DM      256           // D = 2E
#define HHs     512           // H/... LSTM hidden half? (H = 512)
#define G4      2048          // 4H

// ---------------- scratch (static device globals; no allocation) ----------------
__device__ float g_query_n[BQ * DM];
__device__ float g_supp_n[BS * DM];
__device__ float g_query_g[BQ * DM];
__device__ float g_h1[BQ * HHs];
__device__ float g_hpre[BQ * DM];
__device__ float g_support_g[DM];
__device__ float g_sg_norm;
__device__ float g_whh_sg[G4];
__device__ float g_zq[(size_t)BQ * G4];
__device__ float g_z[(size_t)BQ * G4];
__device__ float g_h[BQ * DM];
__device__ float g_c[BQ * HHs];

// ---------------- helpers ----------------
__device__ __forceinline__ float warp_sum(float v) {
#pragma unroll
    for (int o = 16; o; o >>= 1) v += __shfl_down_sync(0xffffffffu, v, o);
    return v;
}

__device__ __forceinline__ float block_reduce(float v, float* red) {
    int t = threadIdx.x;
    red[t] = v;
    __syncthreads();
#pragma unroll
    for (int s = 128; s > 0; s >>= 1) {
        if (t < s) red[t] += red[t + s];
        __syncthreads();
    }
    float r = red[0];
    __syncthreads();
    return r;
}

__device__ __forceinline__ float sigf(float x) { return 1.f / (1.f + expf(-x)); }

// ---------------- kernel 1: neighbor encoder (one block per row-side) ----------------
__global__ __launch_bounds__(256) void neighbor_enc_kernel(
    const float* __restrict__ emb, const float* __restrict__ gcn_W,
    const float* __restrict__ gcn_wb, const float* __restrict__ gate_W,
    const float* __restrict__ gate_b, const int* __restrict__ query,
    const int* __restrict__ support, const int* __restrict__ qlc,
    const int* __restrict__ qrc, const int* __restrict__ slc,
    const int* __restrict__ src_, const int* __restrict__ knn_tab)
{
    __shared__ float cs[EE];
    __shared__ float pv[EE];
    __shared__ float sim[NN];
    __shared__ int   entid[NN];
    __shared__ float sim2[KT];
    __shared__ int   kid[KT];
    __shared__ int   selflag[NN];
    __shared__ int   selA[KK], selR[KK], selK[KK];
    __shared__ float cm[2 * EE];     // [rel_mean | ent_mean]
    __shared__ float km[EE];
    __shared__ float strv[EE], knm[EE];
    __shared__ float red[256];
    __shared__ float s_ncc, s_alpha;

    int b = blockIdx.x, t = threadIdx.x;
    int lane = t & 31, warp = t >> 5;

    const int* conn; int eid; float* dst; int row;
    if (b < BQ)                 { row = b;             conn = qlc  + row * NN * 2; eid = query[2 * row];       dst = g_query_n + row * DM; }
    else if (b < 2 * BQ)        { row = b - BQ;        conn = qrc  + row * NN * 2; eid = query[2 * row + 1];   dst = g_query_n + row * DM + EE; }
    else if (b < 2 * BQ + BS)   { row = b - 2 * BQ;    conn = slc  + row * NN * 2; eid = support[2 * row];     dst = g_supp_n  + row * DM; }
    else                        { row = b - 2 * BQ - BS; conn = src_ + row * NN * 2; eid = support[2 * row + 1]; dst = g_supp_n  + row * DM + EE; }
    if (eid < 0 || eid >= VV) eid = PAD_ID;

    if (t < EE) {
        cs[t] = emb[(size_t)eid * EE + t];
        pv[t] = emb[(size_t)PAD_ID * EE + t];
    }
    if (t < KT) {
        int k = knn_tab[(size_t)eid * KT + t];
        if (k < 0 || k >= VV) k = PAD_ID;
        kid[t] = k;
    }
    __syncthreads();

    // center norm
    float p = (t < EE) ? cs[t] * cs[t] : 0.f;
    float csum = block_reduce(p, red);
    if (t == 0) s_ncc = fmaxf(sqrtf(csum), 1e-8f);
    __syncthreads();
    float ncc = s_ncc;

    const float4* emb4 = (const float4*)emb;
    const float4* cs4  = (const float4*)cs;
    float4 c4 = cs4[lane];

    // ---- pass A: cosine sims for the 128 structural neighbors (warp per neighbor)
#pragma unroll 2
    for (int it = 0; it < NN / 8; it++) {
        int n = it * 8 + warp;
        int ent = conn[2 * n + 1];
        float4 v = emb4[(size_t)ent * 32 + lane];
        float d = v.x * c4.x + v.y * c4.y + v.z * c4.z + v.w * c4.w;
        float q = v.x * v.x + v.y * v.y + v.z * v.z + v.w * v.w;
        d = warp_sum(d); q = warp_sum(q);
        if (lane == 0) { sim[n] = d / (fmaxf(sqrtf(q), 1e-8f) * ncc); entid[n] = ent; }
    }
    __syncthreads();

    // ---- pass B: exact top-32 via rank counting (matches lax.top_k tie-break)
    if (t < NN) {
        float si = sim[t]; int r = 0;
#pragma unroll 8
        for (int j = 0; j < NN; j++) {
            float sj = sim[j];
            r += (sj > si) || (sj == si && j < t);
        }
        selflag[t] = (r < KK) ? 1 : 0;
    }
    __syncthreads();
    if (t < NN && selflag[t]) {
        int pos = 0;
        for (int j = 0; j < t; j++) pos += selflag[j];
        selA[pos] = entid[t];
        selR[pos] = conn[2 * t];     // rel id, only gathered for selected
    }
    __syncthreads();

    // ---- pass C: accumulate rel/ent means (feature-per-thread, deterministic order)
    if (t < EE) {
        float acc = 0.f;
#pragma unroll 4
        for (int s = 0; s < KK; s++) acc += emb[(size_t)selA[s] * EE + t];
        cm[EE + t] = acc * (1.f / KK);          // ent mean -> cat[128:256]
    } else {
        int f = t - EE;
        float acc = 0.f;
#pragma unroll 4
        for (int s = 0; s < KK; s++) acc += emb[(size_t)selR[s] * EE + f];
        cm[f] = acc * (1.f / KK);               // rel mean -> cat[0:128]
    }

    // ---- pass D: knn sims (64), rank top-32, accumulate
#pragma unroll 2
    for (int it = 0; it < KT / 8; it++) {
        int n = it * 8 + warp;
        int ent = kid[n];
        float4 v = emb4[(size_t)ent * 32 + lane];
        float d = v.x * c4.x + v.y * c4.y + v.z * c4.z + v.w * c4.w;
        float q = v.x * v.x + v.y * v.y + v.z * v.z + v.w * v.w;
        d = warp_sum(d); q = warp_sum(q);
        if (lane == 0) sim2[n] = d / (fmaxf(sqrtf(q), 1e-8f) * ncc);
    }
    __syncthreads();
    if (t < KT) {
        float si = sim2[t]; int r = 0;
#pragma unroll 8
        for (int j = 0; j < KT; j++) {
            float sj = sim2[j];
            r += (sj > si) || (sj == si && j < t);
        }
        selflag[t] = (r < KK) ? 1 : 0;
    }
    __syncthreads();
    if (t < KT && selflag[t]) {
        int pos = 0;
        for (int j = 0; j < t; j++) pos += selflag[j];
        selK[pos] = kid[t];
    }
    __syncthreads();
    if (t < EE) {
        float acc = 0.f;
#pragma unroll 4
        for (int s = 0; s < KK; s++) acc += emb[(size_t)selK[s] * EE + t];
        km[t] = acc * (1.f / KK);
    }
    __syncthreads();

    // ---- pass E: GCN matvecs (mean commutes with linear map). warp per output e.
#pragma unroll 1
    for (int i = 0; i < EE / 8; i++) {
        int e = warp + 8 * i;
        const float* wrow = gcn_W + e * 2 * EE;
        float a1 = 0.f, a2 = 0.f;
#pragma unroll
        for (int jj = 0; jj < 8; jj++) {
            int d = lane + 32 * jj;
            a1 += cm[d] * wrow[d];
        }
#pragma unroll
        for (int jj = 0; jj < 4; jj++) {
            int d = lane + 32 * jj;
            a2 += km[d] * wrow[EE + d] + pv[d] * wrow[d];  // pad-rel half + knn half
        }
        a1 = warp_sum(a1); a2 = warp_sum(a2);
        if (lane == 0) {
            strv[e] = tanhf(a1 + gcn_wb[e]);
            knm[e]  = tanhf(a2 + gcn_wb[e]);
        }
    }
    __syncthreads();

    // ---- gate + output
    float gp = (t < EE) ? (strv[t] * gate_W[t] + knm[t] * gate_W[EE + t]) : 0.f;
    float gl = block_reduce(gp, red);
    if (t == 0) s_alpha = sigf(gl + gate_b[0]);
    __syncthreads();
    float a = s_alpha;
    if (t < EE) dst[t] = (1.f - a) * strv[t] + a * knm[t];
}

// ---------------- kernel 2: support encoder (5 rows) + mean + norm ----------------
__global__ __launch_bounds__(256) void support_enc_kernel(
    const float* __restrict__ se_w1, const float* __restrict__ se_b1,
    const float* __restrict__ se_w2, const float* __restrict__ se_b2,
    const float* __restrict__ ln_g, const float* __restrict__ ln_b)
{
    __shared__ float xs[BS][DM];
    __shared__ float h1s[BS][HHs];
    __shared__ float hrow[BS][DM];
    __shared__ float red[256];
    int t = threadIdx.x;

    for (int idx = t; idx < BS * DM; idx += 256) xs[idx / DM][idx % DM] = g_supp_n[idx];
    __syncthreads();

    // stage 1: h1 = relu(x @ w1^T + b1) for all 5 rows simultaneously
#pragma unroll
    for (int h = 0; h < 2; h++) {
        int n = t + h * 256;
        float acc[BS] = {0, 0, 0, 0, 0};
        const float* wr = se_w1 + (size_t)n * DM;
        for (int k = 0; k < DM; k++) {
            float w = wr[k];
#pragma unroll
            for (int r = 0; r < BS; r++) acc[r] += xs[r][k] * w;
        }
        float bb = se_b1[n];
#pragma unroll
        for (int r = 0; r < BS; r++) h1s[r][n] = fmaxf(acc[r] + bb, 0.f);
    }
    __syncthreads();

    // stage 2: h = h1 @ w2^T + b2 + x
    {
        float acc[BS] = {0, 0, 0, 0, 0};
        const float* wr = se_w2 + (size_t)t * HHs;
        for (int k = 0; k < HHs; k++) {
            float w = wr[k];
#pragma unroll
            for (int r = 0; r < BS; r++) acc[r] += h1s[r][k] * w;
        }
        float bb = se_b2[t];
#pragma unroll
        for (int r = 0; r < BS; r++) hrow[r][t] = acc[r] + bb + xs[r][t];
    }
    __syncthreads();

    // LN per row, then mean over rows
    float ssum = 0.f;
    for (int r = 0; r < BS; r++) {
        float x = hrow[r][t];
        float mu = block_reduce(x, red) * (1.f / DM);
        float dx = x - mu;
        float var = block_reduce(dx * dx, red) * (1.f / DM);
        ssum += dx * rsqrtf(var + 1e-5f) * ln_g[t] + ln_b[t];
    }
    float sg = ssum * (1.f / BS);
    g_support_g[t] = sg;
    float nrm = block_reduce(sg * sg, red);
    if (t == 0) g_sg_norm = fmaxf(sqrtf(nrm), 1e-12f);
}

// ---------------- kernel 3: whh_sg[n] = sum_j W_hh[n, 256+j] * support_g[j] ----------------
__global__ __launch_bounds__(256) void whh_sg_kernel(const float* __restrict__ W_hh)
{
    int warp = threadIdx.x >> 5, lane = threadIdx.x & 31;
    int n = blockIdx.x * 8 + warp;
    const float* wr = W_hh + (size_t)n * HHs + DM;
    float acc = 0.f;
#pragma unroll
    for (int jj = 0; jj < 8; jj++) {
        int j = lane + 32 * jj;
        acc += wr[j] * g_support_g[j];
    }
    acc = warp_sum(acc);
    if (lane == 0) g_whh_sg[n] = acc;
}

// ---------------- tiled fp32 GEMM:  C[m,n] = sum_k A[m,k] * B[n,k]  (+ epilogue) ----------------
// mode 0: plain  | 1: relu(+bias)  | 2: +bias +add[m,n]  | 3: +bias +bias2
__global__ __launch_bounds__(256) void sgemm_nt_kernel(
    const float* __restrict__ A, int lda, const float* __restrict__ B, int ldb,
    float* __restrict__ C, int M, int N, int K, int mode,
    const float* __restrict__ bias, const float* __restrict__ bias2,
    const float* __restrict__ add)
{
    const int BM = 128, BN = 128, BK = 16;
    __shared__ float As[BK][BM + 4];
    __shared__ float Bs[BK][BN + 4];
    int tid = threadIdx.x;
    int bm = blockIdx.y * BM, bn = blockIdx.x * BN;
    int tx = tid & 15, ty = tid >> 4;

    float acc[8][8];
#pragma unroll
    for (int i = 0; i < 8; i++)
#pragma unroll
        for (int j = 0; j < 8; j++) acc[i][j] = 0.f;

    int lrow = tid >> 2;            // 0..63
    int lcol = (tid & 3) * 4;       // 0,4,8,12

    for (int k0 = 0; k0 < K; k0 += BK) {
#pragma unroll
        for (int h = 0; h < 2; h++) {
            int r = lrow + h * 64;
            float4 v = *(const float4*)(A + (size_t)(bm + r) * lda + k0 + lcol);
            As[lcol + 0][r] = v.x; As[lcol + 1][r] = v.y;
            As[lcol + 2][r] = v.z; As[lcol + 3][r] = v.w;
        }
#pragma unroll
        for (int h = 0; h < 2; h++) {
            int r = lrow + h * 64;
            float4 v = *(const float4*)(B + (size_t)(bn + r) * ldb + k0 + lcol);
            Bs[lcol + 0][r] = v.x; Bs[lcol + 1][r] = v.y;
            Bs[lcol + 2][r] = v.z; Bs[lcol + 3][r] = v.w;
        }
        __syncthreads();
#pragma unroll
        for (int k = 0; k < BK; k++) {
            float a[8], bb[8];
#pragma unroll
            for (int i = 0; i < 8; i++) a[i] = As[k][ty * 8 + i];
#pragma unroll
            for (int j = 0; j < 8; j++) bb[j] = Bs[k][tx * 8 + j];
#pragma unroll
            for (int i = 0; i < 8; i++)
#pragma unroll
                for (int j = 0; j < 8; j++) acc[i][j] += a[i] * bb[j];
        }
        __syncthreads();
    }

#pragma unroll
    for (int i = 0; i < 8; i++) {
        int m = bm + ty * 8 + i;
#pragma unroll
        for (int j = 0; j < 8; j++) {
            int n = bn + tx * 8 + j;
            float v = acc[i][j];
            if (mode == 1)      v = fmaxf(v + bias[n], 0.f);
            else if (mode == 2) v = v + bias[n] + add[(size_t)m * N + n];
            else if (mode == 3) v = v + bias[n] + bias2[n];
            C[(size_t)m * N + n] = v;
        }
    }
}

// ---------------- LayerNorm over 256 features (one block per row) ----------------
__global__ __launch_bounds__(256) void ln_kernel(const float* __restrict__ ln_g,
                                                 const float* __restrict__ ln_b)
{
    __shared__ float red[256];
    int m = blockIdx.x, t = threadIdx.x;
    float x = g_hpre[m * DM + t];
    float mu = block_reduce(x, red) * (1.f / DM);
    float dx = x - mu;
    float var = block_reduce(dx * dx, red) * (1.f / DM);
    g_query_g[m * DM + t] = dx * rsqrtf(var + 1e-5f) * ln_g[t] + ln_b[t];
}

// ---------------- LSTM cell elementwise ----------------
__global__ __launch_bounds__(256) void lstm_cell_kernel(const float* __restrict__ z, int first)
{
    int idx = blockIdx.x * 256 + threadIdx.x;
    int m = idx >> 9, j = idx & 511;
    const float* zr = z + (size_t)m * G4;
    float iv = zr[j], fv = zr[512 + j], gv = zr[1024 + j], ov = zr[1536 + j];
    float cp = first ? 0.f : g_c[idx];
    float c2 = sigf(fv) * cp + sigf(iv) * tanhf(gv);
    g_c[idx] = c2;
    if (j < DM) {
        float h2 = sigf(ov) * tanhf(c2);
        g_h[m * DM + j] = g_query_g[m * DM + j] + h2;
    }
}

// ---------------- final cosine score ----------------
__global__ __launch_bounds__(256) void final_kernel(float* __restrict__ out)
{
    int warp = threadIdx.x >> 5, lane = threadIdx.x & 31;
    int m = blockIdx.x * 8 + warp;
    float d = 0.f, hh = 0.f;
#pragma unroll
    for (int jj = 0; jj < 8; jj++) {
        int j = lane + 32 * jj;
        float hv = g_h[m * DM + j];
        d += hv * g_support_g[j];
        hh += hv * hv;
    }
    d = warp_sum(d); hh = warp_sum(hh);
    if (lane == 0) out[m] = d / (fmaxf(sqrtf(hh), 1e-12f) * g_sg_norm);
}

// ---------------- launch ----------------
extern "C" void kernel_launch(void* const* d_in, const int* in_sizes, int n_in,
                              void* d_out, int out_size)
{
    const float* emb     = (const float*)d_in[0];
    const float* gcn_W   = (const float*)d_in[1];
    const float* gcn_wb  = (const float*)d_in[2];
    const float* gate_W  = (const float*)d_in[3];
    const float* gate_b  = (const float*)d_in[4];
    const float* se_w1   = (const float*)d_in[5];
    const float* se_b1   = (const float*)d_in[6];
    const float* se_w2   = (const float*)d_in[7];
    const float* se_b2   = (const float*)d_in[8];
    const float* ln_g    = (const float*)d_in[9];
    const float* ln_b    = (const float*)d_in[10];
    const float* W_ih    = (const float*)d_in[11];
    const float* W_hh    = (const float*)d_in[12];
    const float* b_ih    = (const float*)d_in[13];
    const float* b_hh    = (const float*)d_in[14];
    const int*   query   = (const int*)d_in[15];
    const int*   support = (const int*)d_in[16];
    const int*   qlc     = (const int*)d_in[17];
    const int*   qrc     = (const int*)d_in[19];
    const int*   slc     = (const int*)d_in[21];
    const int*   src_    = (const int*)d_in[23];
    const int*   knn_tab = (const int*)d_in[25];
    float* out = (float*)d_out;

    float *p_qn, *p_qg, *p_h1, *p_hpre, *p_zq, *p_z, *p_h, *p_whhsg;
    cudaGetSymbolAddress((void**)&p_qn,    g_query_n);
    cudaGetSymbolAddress((void**)&p_qg,    g_query_g);
    cudaGetSymbolAddress((void**)&p_h1,    g_h1);
    cudaGetSymbolAddress((void**)&p_hpre,  g_hpre);
    cudaGetSymbolAddress((void**)&p_zq,    g_zq);
    cudaGetSymbolAddress((void**)&p_z,     g_z);
    cudaGetSymbolAddress((void**)&p_h,     g_h);
    cudaGetSymbolAddress((void**)&p_whhsg, g_whh_sg);

    // 1. neighbor encoders (q_l, q_r, s_l, s_r)
    neighbor_enc_kernel<<<2 * BQ + 2 * BS, 256>>>(emb, gcn_W, gcn_wb, gate_W, gate_b,
                                                  query, support, qlc, qrc, slc, src_, knn_tab);
    // 2. support SE + mean + norm
    support_enc_kernel<<<1, 256>>>(se_w1, se_b1, se_w2, se_b2, ln_g, ln_b);
    // 3. support contribution to LSTM recurrent term
    whh_sg_kernel<<<G4 / 8, 256>>>(W_hh);

    // 4. query SE: h1 = relu(qn @ w1^T + b1) ; hpre = h1 @ w2^T + b2 + qn ; LN
    {
        dim3 g1(HHs / 128, BQ / 128);
        sgemm_nt_kernel<<<g1, 256>>>(p_qn, DM, se_w1, DM, p_h1, BQ, HHs, DM, 1, se_b1, nullptr, nullptr);
        dim3 g2(DM / 128, BQ / 128);
        sgemm_nt_kernel<<<g2, 256>>>(p_h1, HHs, se_w2, HHs, p_hpre, BQ, DM, HHs, 2, se_b2, nullptr, p_qn);
        ln_kernel<<<BQ, 256>>>(ln_g, ln_b);
    }

    // 5. zq = query_g @ W_ih^T + b_ih + b_hh   (step-invariant)
    dim3 g3(G4 / 128, BQ / 128);
    sgemm_nt_kernel<<<g3, 256>>>(p_qg, DM, W_ih, DM, p_zq, BQ, G4, DM, 3, b_ih, b_hh, nullptr);

    // 6. step 1: h_r = 0 -> z = zq directly (no GEMM)
    lstm_cell_kernel<<<(BQ * HHs) / 256, 256>>>(p_zq, 1);

    // 7. steps 2..4: z = zq + h @ W_hh[:, :256]^T + whh_sg
    for (int s = 0; s < 3; s++) {
        sgemm_nt_kernel<<<g3, 256>>>(p_h, DM, W_hh, HHs, p_z, BQ, G4, DM, 2, p_whhsg, nullptr, p_zq);
        lstm_cell_kernel<<<(BQ * HHs) / 256, 256>>>(p_z, 0);
    }

    // 8. cosine score
    final_kernel<<<BQ / 8, 256>>>(out);
}

// round 2
// speedup vs baseline: 1.3039x; 1.3039x over previous
#include <cuda_runtime.h>
#include <math.h>

#define VV      200000
#define EE      128
#define PAD_ID  199999
#define KK      32            // KNN_K
#define BQ      2048
#define BS      5
#define NN      128
#define KT      64
#define DM      256           // D = 2E
#define HHs     512           // H/2 = 512 (H = 1024 split as [h | r])
#define G4      2048          // 4H gates dim

// ---------------- scratch (static device globals; no allocation) ----------------
__device__ float g_query_n[BQ * DM];
__device__ float g_supp_n[BS * DM];
__device__ float g_se_supp[BS * DM];
__device__ float g_query_g[BQ * DM];
__device__ float g_h1[BQ * HHs];
__device__ float g_hpre[BQ * DM];
__device__ float g_support_g[DM];
__device__ float g_sg_norm;
__device__ float g_whh_sg[G4];
__device__ float g_zq[(size_t)BQ * G4];
__device__ float g_z[(size_t)BQ * G4];
__device__ float g_h[BQ * DM];
__device__ float g_c[BQ * HHs];

// ---------------- helpers ----------------
__device__ __forceinline__ float warp_sum(float v) {
#pragma unroll
    for (int o = 16; o; o >>= 1) v += __shfl_down_sync(0xffffffffu, v, o);
    return v;
}

__device__ __forceinline__ float block_reduce(float v, float* red) {
    int t = threadIdx.x;
    red[t] = v;
    __syncthreads();
#pragma unroll
    for (int s = 128; s > 0; s >>= 1) {
        if (t < s) red[t] += red[t + s];
        __syncthreads();
    }
    float r = red[0];
    __syncthreads();
    return r;
}

__device__ __forceinline__ float sigf(float x) { return 1.f / (1.f + expf(-x)); }

__device__ __forceinline__ float to_tf32(float x) {
    float r;
    asm("cvt.rna.tf32.f32 %0, %1;" : "=f"(r) : "f"(x));
    return r;
}

// ---------------- kernel 1: neighbor encoder (one block per row-side) ----------------
__global__ __launch_bounds__(256) void neighbor_enc_kernel(
    const float* __restrict__ emb, const float* __restrict__ gcn_W,
    const float* __restrict__ gcn_wb, const float* __restrict__ gate_W,
    const float* __restrict__ gate_b, const int* __restrict__ query,
    const int* __restrict__ support, const int* __restrict__ qlc,
    const int* __restrict__ qrc, const int* __restrict__ slc,
    const int* __restrict__ src_, const int* __restrict__ knn_tab)
{
    __shared__ float cs[EE];
    __shared__ float pv[EE];
    __shared__ float sim[NN];
    __shared__ int   entid[NN];
    __shared__ float sim2[KT];
    __shared__ int   kid[KT];
    __shared__ int   selflag[NN];
    __shared__ int   selA[KK], selR[KK], selK[KK];
    __shared__ float cm[2 * EE];     // [rel_mean | ent_mean]
    __shared__ float km[EE];
    __shared__ float strv[EE], knm[EE];
    __shared__ float red[256];
    __shared__ float s_ncc, s_alpha;

    int b = blockIdx.x, t = threadIdx.x;
    int lane = t & 31, warp = t >> 5;

    const int* conn; int eid; float* dst; int row;
    if (b < BQ)                 { row = b;             conn = qlc  + row * NN * 2; eid = query[2 * row];       dst = g_query_n + row * DM; }
    else if (b < 2 * BQ)        { row = b - BQ;        conn = qrc  + row * NN * 2; eid = query[2 * row + 1];   dst = g_query_n + row * DM + EE; }
    else if (b < 2 * BQ + BS)   { row = b - 2 * BQ;    conn = slc  + row * NN * 2; eid = support[2 * row];     dst = g_supp_n  + row * DM; }
    else                        { row = b - 2 * BQ - BS; conn = src_ + row * NN * 2; eid = support[2 * row + 1]; dst = g_supp_n  + row * DM + EE; }
    if (eid < 0 || eid >= VV) eid = PAD_ID;

    if (t < EE) {
        cs[t] = emb[(size_t)eid * EE + t];
        pv[t] = emb[(size_t)PAD_ID * EE + t];
    }
    if (t < KT) {
        int k = knn_tab[(size_t)eid * KT + t];
        if (k < 0 || k >= VV) k = PAD_ID;
        kid[t] = k;
    }
    __syncthreads();

    // center norm
    float p = (t < EE) ? cs[t] * cs[t] : 0.f;
    float csum = block_reduce(p, red);
    if (t == 0) s_ncc = fmaxf(sqrtf(csum), 1e-8f);
    __syncthreads();
    float ncc = s_ncc;

    const float4* emb4 = (const float4*)emb;
    const float4* cs4  = (const float4*)cs;
    float4 c4 = cs4[lane];

    // ---- pass A: cosine sims for the 128 structural neighbors (warp per neighbor)
#pragma unroll 2
    for (int it = 0; it < NN / 8; it++) {
        int n = it * 8 + warp;
        int ent = conn[2 * n + 1];
        float4 v = emb4[(size_t)ent * 32 + lane];
        float d = v.x * c4.x + v.y * c4.y + v.z * c4.z + v.w * c4.w;
        float q = v.x * v.x + v.y * v.y + v.z * v.z + v.w * v.w;
        d = warp_sum(d); q = warp_sum(q);
        if (lane == 0) { sim[n] = d / (fmaxf(sqrtf(q), 1e-8f) * ncc); entid[n] = ent; }
    }
    __syncthreads();

    // ---- pass B: exact top-32 via rank counting (matches lax.top_k tie-break)
    if (t < NN) {
        float si = sim[t]; int r = 0;
#pragma unroll 8
        for (int j = 0; j < NN; j++) {
            float sj = sim[j];
            r += (sj > si) || (sj == si && j < t);
        }
        selflag[t] = (r < KK) ? 1 : 0;
    }
    __syncthreads();
    if (t < NN && selflag[t]) {
        int pos = 0;
        for (int j = 0; j < t; j++) pos += selflag[j];
        selA[pos] = entid[t];
        selR[pos] = conn[2 * t];     // rel id, only gathered for selected
    }
    __syncthreads();

    // ---- pass C: accumulate rel/ent means (feature-per-thread, deterministic order)
    if (t < EE) {
        float acc = 0.f;
#pragma unroll 4
        for (int s = 0; s < KK; s++) acc += emb[(size_t)selA[s] * EE + t];
        cm[EE + t] = acc * (1.f / KK);          // ent mean -> cat[128:256]
    } else {
        int f = t - EE;
        float acc = 0.f;
#pragma unroll 4
        for (int s = 0; s < KK; s++) acc += emb[(size_t)selR[s] * EE + f];
        cm[f] = acc * (1.f / KK);               // rel mean -> cat[0:128]
    }

    // ---- pass D: knn sims (64), rank top-32, accumulate
#pragma unroll 2
    for (int it = 0; it < KT / 8; it++) {
        int n = it * 8 + warp;
        int ent = kid[n];
        float4 v = emb4[(size_t)ent * 32 + lane];
        float d = v.x * c4.x + v.y * c4.y + v.z * c4.z + v.w * c4.w;
        float q = v.x * v.x + v.y * v.y + v.z * v.z + v.w * v.w;
        d = warp_sum(d); q = warp_sum(q);
        if (lane == 0) sim2[n] = d / (fmaxf(sqrtf(q), 1e-8f) * ncc);
    }
    __syncthreads();
    if (t < KT) {
        float si = sim2[t]; int r = 0;
#pragma unroll 8
        for (int j = 0; j < KT; j++) {
            float sj = sim2[j];
            r += (sj > si) || (sj == si && j < t);
        }
        selflag[t] = (r < KK) ? 1 : 0;
    }
    __syncthreads();
    if (t < KT && selflag[t]) {
        int pos = 0;
        for (int j = 0; j < t; j++) pos += selflag[j];
        selK[pos] = kid[t];
    }
    __syncthreads();
    if (t < EE) {
        float acc = 0.f;
#pragma unroll 4
        for (int s = 0; s < KK; s++) acc += emb[(size_t)selK[s] * EE + t];
        km[t] = acc * (1.f / KK);
    }
    __syncthreads();

    // ---- pass E: GCN matvecs (mean commutes with linear map). warp per output e.
#pragma unroll 1
    for (int i = 0; i < EE / 8; i++) {
        int e = warp + 8 * i;
        const float* wrow = gcn_W + e * 2 * EE;
        float a1 = 0.f, a2 = 0.f;
#pragma unroll
        for (int jj = 0; jj < 8; jj++) {
            int d = lane + 32 * jj;
            a1 += cm[d] * wrow[d];
        }
#pragma unroll
        for (int jj = 0; jj < 4; jj++) {
            int d = lane + 32 * jj;
            a2 += km[d] * wrow[EE + d] + pv[d] * wrow[d];  // pad-rel half + knn half
        }
        a1 = warp_sum(a1); a2 = warp_sum(a2);
        if (lane == 0) {
            strv[e] = tanhf(a1 + gcn_wb[e]);
            knm[e]  = tanhf(a2 + gcn_wb[e]);
        }
    }
    __syncthreads();

    // ---- gate + output
    float gp = (t < EE) ? (strv[t] * gate_W[t] + knm[t] * gate_W[EE + t]) : 0.f;
    float gl = block_reduce(gp, red);
    if (t == 0) s_alpha = sigf(gl + gate_b[0]);
    __syncthreads();
    float a = s_alpha;
    if (t < EE) dst[t] = (1.f - a) * strv[t] + a * knm[t];
}

// ---------------- kernel 2a: support encoder, one block per support row ----------------
__global__ __launch_bounds__(256) void support_row_kernel(
    const float* __restrict__ se_w1, const float* __restrict__ se_b1,
    const float* __restrict__ se_w2, const float* __restrict__ se_b2,
    const float* __restrict__ ln_g, const float* __restrict__ ln_b)
{
    __shared__ float xs[DM];
    __shared__ float h1s[HHs];
    __shared__ float red[256];
    int r = blockIdx.x, t = threadIdx.x;

    xs[t] = g_supp_n[r * DM + t];
    __syncthreads();

    // h1 = relu(x @ w1^T + b1)
#pragma unroll
    for (int h = 0; h < 2; h++) {
        int n = t + h * 256;
        const float* wr = se_w1 + (size_t)n * DM;
        float acc = 0.f;
        for (int k = 0; k < DM; k++) acc += xs[k] * wr[k];
        h1s[n] = fmaxf(acc + se_b1[n], 0.f);
    }
    __syncthreads();

    // h = h1 @ w2^T + b2 + x, then LN
    const float* wr = se_w2 + (size_t)t * HHs;
    float acc = 0.f;
    for (int k = 0; k < HHs; k++) acc += h1s[k] * wr[k];
    float x = acc + se_b2[t] + xs[t];

    float mu = block_reduce(x, red) * (1.f / DM);
    float dx = x - mu;
    float var = block_reduce(dx * dx, red) * (1.f / DM);
    g_se_supp[r * DM + t] = dx * rsqrtf(var + 1e-5f) * ln_g[t] + ln_b[t];
}

// ---------------- kernel 2b: mean over support rows + norm ----------------
__global__ __launch_bounds__(256) void support_reduce_kernel()
{
    __shared__ float red[256];
    int t = threadIdx.x;
    float s = 0.f;
#pragma unroll
    for (int r = 0; r < BS; r++) s += g_se_supp[r * DM + t];
    float sg = s * (1.f / BS);
    g_support_g[t] = sg;
    float nrm = block_reduce(sg * sg, red);
    if (t == 0) g_sg_norm = fmaxf(sqrtf(nrm), 1e-12f);
}

// ---------------- kernel 3: whh_sg[n] = sum_j W_hh[n, 256+j] * support_g[j] ----------------
__global__ __launch_bounds__(256) void whh_sg_kernel(const float* __restrict__ W_hh)
{
    int warp = threadIdx.x >> 5, lane = threadIdx.x & 31;
    int n = blockIdx.x * 8 + warp;
    const float* wr = W_hh + (size_t)n * HHs + DM;
    float acc = 0.f;
#pragma unroll
    for (int jj = 0; jj < 8; jj++) {
        int j = lane + 32 * jj;
        acc += wr[j] * g_support_g[j];
    }
    acc = warp_sum(acc);
    if (lane == 0) g_whh_sg[n] = acc;
}

// ---------------- tf32 tensor-core GEMM:  C[m,n] = sum_k A[m,k]*B[n,k]  (+ epilogue) ----------------
// mode 0: plain | 1: relu(+bias) | 2: +bias +add[m,n] | 3: +bias +bias2
// Tiles: BM=128, BN=64, BK=32. 8 warps as 4(M)x2(N), each warp 32x32 via 2x4 mma m16n8k8.
__global__ __launch_bounds__(256) void tf32_gemm_nt(
    const float* __restrict__ A, int lda, const float* __restrict__ B, int ldb,
    float* __restrict__ C, int M, int N, int K, int mode,
    const float* __restrict__ bias, const float* __restrict__ bias2,
    const float* __restrict__ add)
{
    const int LDSA = 136;   // 136 % 32 == 8 -> conflict-free fragment reads
    const int LDSB = 72;    // 72 % 32 == 8
    __shared__ float As[32][LDSA];
    __shared__ float Bs[32][LDSB];

    int tid = threadIdx.x;
    int lane = tid & 31, wid = tid >> 5;
    int bm = blockIdx.y * 128, bn = blockIdx.x * 64;
    int wm = (wid >> 1) * 32;   // warp M offset in tile
    int wn = (wid & 1) * 32;    // warp N offset in tile
    int r0 = lane >> 2, q = lane & 3;

    float c[2][4][4];
#pragma unroll
    for (int mt = 0; mt < 2; mt++)
#pragma unroll
        for (int nt = 0; nt < 4; nt++)
#pragma unroll
            for (int i = 0; i < 4; i++) c[mt][nt][i] = 0.f;

    int ar = tid >> 1;            // 0..127
    int ac = (tid & 1) * 16;      // 0 or 16
    int br = tid >> 2;            // 0..63
    int bc = (tid & 3) * 8;       // 0,8,16,24

    for (int kt = 0; kt < K; kt += 32) {
        // load + convert A tile [128 x 32]
        const float* Arow = A + (size_t)(bm + ar) * lda + kt + ac;
#pragma unroll
        for (int i = 0; i < 4; i++) {
            float4 v = *(const float4*)(Arow + i * 4);
            int k = ac + i * 4;
            As[k + 0][ar] = to_tf32(v.x); As[k + 1][ar] = to_tf32(v.y);
            As[k + 2][ar] = to_tf32(v.z); As[k + 3][ar] = to_tf32(v.w);
        }
        // load + convert B tile [64 x 32] (transposed into [k][n])
        const float* Brow = B + (size_t)(bn + br) * ldb + kt + bc;
#pragma unroll
        for (int i = 0; i < 2; i++) {
            float4 v = *(const float4*)(Brow + i * 4);
            int k = bc + i * 4;
            Bs[k + 0][br] = to_tf32(v.x); Bs[k + 1][br] = to_tf32(v.y);
            Bs[k + 2][br] = to_tf32(v.z); Bs[k + 3][br] = to_tf32(v.w);
        }
        __syncthreads();

#pragma unroll
        for (int k0 = 0; k0 < 32; k0 += 8) {
            unsigned a[2][4], bfr[4][2];
#pragma unroll
            for (int mt = 0; mt < 2; mt++) {
                int m = wm + mt * 16 + r0;
                a[mt][0] = __float_as_uint(As[k0 + q][m]);
                a[mt][1] = __float_as_uint(As[k0 + q][m + 8]);
                a[mt][2] = __float_as_uint(As[k0 + q + 4][m]);
                a[mt][3] = __float_as_uint(As[k0 + q + 4][m + 8]);
            }
#pragma unroll
            for (int nt = 0; nt < 4; nt++) {
                int n = wn + nt * 8 + r0;
                bfr[nt][0] = __float_as_uint(Bs[k0 + q][n]);
                bfr[nt][1] = __float_as_uint(Bs[k0 + q + 4][n]);
            }
#pragma unroll
            for (int mt = 0; mt < 2; mt++)
#pragma unroll
                for (int nt = 0; nt < 4; nt++) {
                    asm volatile(
                        "mma.sync.aligned.m16n8k8.row.col.f32.tf32.tf32.f32 "
                        "{%0,%1,%2,%3}, {%4,%5,%6,%7}, {%8,%9}, {%0,%1,%2,%3};"
                        : "+f"(c[mt][nt][0]), "+f"(c[mt][nt][1]),
                          "+f"(c[mt][nt][2]), "+f"(c[mt][nt][3])
                        : "r"(a[mt][0]), "r"(a[mt][1]), "r"(a[mt][2]), "r"(a[mt][3]),
                          "r"(bfr[nt][0]), "r"(bfr[nt][1]));
                }
        }
        __syncthreads();
    }

    // epilogue
#pragma unroll
    for (int mt = 0; mt < 2; mt++) {
        int mrow = bm + wm + mt * 16 + r0;
#pragma unroll
        for (int nt = 0; nt < 4; nt++) {
            int ncol = bn + wn + nt * 8 + 2 * q;
#pragma unroll
            for (int i = 0; i < 4; i++) {
                int m = mrow + (i >> 1) * 8;
                int n = ncol + (i & 1);
                float v = c[mt][nt][i];
                if (mode == 1)      v = fmaxf(v + bias[n], 0.f);
                else if (mode == 2) v = v + bias[n] + add[(size_t)m * N + n];
                else if (mode == 3) v = v + bias[n] + bias2[n];
                C[(size_t)m * N + n] = v;
            }
        }
    }
}

// ---------------- LayerNorm over 256 features (one block per row) ----------------
__global__ __launch_bounds__(256) void ln_kernel(const float* __restrict__ ln_g,
                                                 const float* __restrict__ ln_b)
{
    __shared__ float red[256];
    int m = blockIdx.x, t = threadIdx.x;
    float x = g_hpre[m * DM + t];
    float mu = block_reduce(x, red) * (1.f / DM);
    float dx = x - mu;
    float var = block_reduce(dx * dx, red) * (1.f / DM);
    g_query_g[m * DM + t] = dx * rsqrtf(var + 1e-5f) * ln_g[t] + ln_b[t];
}

// ---------------- LSTM cell elementwise ----------------
__global__ __launch_bounds__(256) void lstm_cell_kernel(const float* __restrict__ z, int first)
{
    int idx = blockIdx.x * 256 + threadIdx.x;
    int m = idx >> 9, j = idx & 511;
    const float* zr = z + (size_t)m * G4;
    float iv = zr[j], fv = zr[512 + j], gv = zr[1024 + j], ov = zr[1536 + j];
    float cp = first ? 0.f : g_c[idx];
    float c2 = sigf(fv) * cp + sigf(iv) * tanhf(gv);
    g_c[idx] = c2;
    if (j < DM) {
        float h2 = sigf(ov) * tanhf(c2);
        g_h[m * DM + j] = g_query_g[m * DM + j] + h2;
    }
}

// ---------------- final cosine score ----------------
__global__ __launch_bounds__(256) void final_kernel(float* __restrict__ out)
{
    int warp = threadIdx.x >> 5, lane = threadIdx.x & 31;
    int m = blockIdx.x * 8 + warp;
    float d = 0.f, hh = 0.f;
#pragma unroll
    for (int jj = 0; jj < 8; jj++) {
        int j = lane + 32 * jj;
        float hv = g_h[m * DM + j];
        d += hv * g_support_g[j];
        hh += hv * hv;
    }
    d = warp_sum(d); hh = warp_sum(hh);
    if (lane == 0) out[m] = d / (fmaxf(sqrtf(hh), 1e-12f) * g_sg_norm);
}

// ---------------- launch ----------------
extern "C" void kernel_launch(void* const* d_in, const int* in_sizes, int n_in,
                              void* d_out, int out_size)
{
    const float* emb     = (const float*)d_in[0];
    const float* gcn_W   = (const float*)d_in[1];
    const float* gcn_wb  = (const float*)d_in[2];
    const float* gate_W  = (const float*)d_in[3];
    const float* gate_b  = (const float*)d_in[4];
    const float* se_w1   = (const float*)d_in[5];
    const float* se_b1   = (const float*)d_in[6];
    const float* se_w2   = (const float*)d_in[7];
    const float* se_b2   = (const float*)d_in[8];
    const float* ln_g    = (const float*)d_in[9];
    const float* ln_b    = (const float*)d_in[10];
    const float* W_ih    = (const float*)d_in[11];
    const float* W_hh    = (const float*)d_in[12];
    const float* b_ih    = (const float*)d_in[13];
    const float* b_hh    = (const float*)d_in[14];
    const int*   query   = (const int*)d_in[15];
    const int*   support = (const int*)d_in[16];
    const int*   qlc     = (const int*)d_in[17];
    const int*   qrc     = (const int*)d_in[19];
    const int*   slc     = (const int*)d_in[21];
    const int*   src_    = (const int*)d_in[23];
    const int*   knn_tab = (const int*)d_in[25];
    float* out = (float*)d_out;

    float *p_qn, *p_qg, *p_h1, *p_hpre, *p_zq, *p_z, *p_h, *p_whhsg;
    cudaGetSymbolAddress((void**)&p_qn,    g_query_n);
    cudaGetSymbolAddress((void**)&p_qg,    g_query_g);
    cudaGetSymbolAddress((void**)&p_h1,    g_h1);
    cudaGetSymbolAddress((void**)&p_hpre,  g_hpre);
    cudaGetSymbolAddress((void**)&p_zq,    g_zq);
    cudaGetSymbolAddress((void**)&p_z,     g_z);
    cudaGetSymbolAddress((void**)&p_h,     g_h);
    cudaGetSymbolAddress((void**)&p_whhsg, g_whh_sg);

    // 1. neighbor encoders (q_l, q_r, s_l, s_r)
    neighbor_enc_kernel<<<2 * BQ + 2 * BS, 256>>>(emb, gcn_W, gcn_wb, gate_W, gate_b,
                                                  query, support, qlc, qrc, slc, src_, knn_tab);
    // 2. support SE (parallel rows) + mean + norm
    support_row_kernel<<<BS, 256>>>(se_w1, se_b1, se_w2, se_b2, ln_g, ln_b);
    support_reduce_kernel<<<1, 256>>>();
    // 3. support contribution to LSTM recurrent term
    whh_sg_kernel<<<G4 / 8, 256>>>(W_hh);

    // 4. query SE: h1 = relu(qn @ w1^T + b1) ; hpre = h1 @ w2^T + b2 + qn ; LN
    {
        dim3 g1(HHs / 64, BQ / 128);
        tf32_gemm_nt<<<g1, 256>>>(p_qn, DM, se_w1, DM, p_h1, BQ, HHs, DM, 1, se_b1, nullptr, nullptr);
        dim3 g2(DM / 64, BQ / 128);
        tf32_gemm_nt<<<g2, 256>>>(p_h1, HHs, se_w2, HHs, p_hpre, BQ, DM, HHs, 2, se_b2, nullptr, p_qn);
        ln_kernel<<<BQ, 256>>>(ln_g, ln_b);
    }

    // 5. zq = query_g @ W_ih^T + b_ih + b_hh   (step-invariant)
    dim3 g3(G4 / 64, BQ / 128);
    tf32_gemm_nt<<<g3, 256>>>(p_qg, DM, W_ih, DM, p_zq, BQ, G4, DM, 3, b_ih, b_hh, nullptr);

    // 6. step 1: h_r = 0 -> z = zq directly (no GEMM)
    lstm_cell_kernel<<<(BQ * HHs) / 256, 256>>>(p_zq, 1);

    // 7. steps 2..4: z = zq + h @ W_hh[:, :256]^T + whh_sg
    for (int s = 0; s < 3; s++) {
        tf32_gemm_nt<<<g3, 256>>>(p_h, DM, W_hh, HHs, p_z, BQ, G4, DM, 2, p_whhsg, nullptr, p_zq);
        lstm_cell_kernel<<<(BQ * HHs) / 256, 256>>>(p_z, 0);
    }

    // 8. cosine score
    final_kernel<<<BQ / 8, 256>>>(out);
}

// round 4
// speedup vs baseline: 1.4220x; 1.0906x over previous
#include <cuda_runtime.h>
#include <math.h>

#define VV      200000
#define EE      128
#define PAD_ID  199999
#define KK      32
#define BQ      2048
#define BS      5
#define NN      128
#define KT      64
#define DM      256
#define HHs     512
#define G4      2048

#define GEMM_SMEM_BYTES 53248   // 2*32*136 + 2*32*72 floats

// ---------------- scratch ----------------
__device__ float g_query_n[BQ * DM];
__device__ float g_supp_n[BS * DM];
__device__ float g_se_supp[BS * DM];
__device__ float g_query_g[BQ * DM];
__device__ float g_h1[BQ * HHs];
__device__ float g_hpre[BQ * DM];
__device__ float g_support_g[DM];
__device__ float g_sg_norm;
__device__ float g_whh_sg[G4];
__device__ float g_zq[(size_t)BQ * G4];
__device__ float g_hA[BQ * DM];
__device__ float g_hB[BQ * DM];
__device__ float g_c[BQ * HHs];

// ---------------- helpers ----------------
__device__ __forceinline__ float warp_sum(float v) {
#pragma unroll
    for (int o = 16; o; o >>= 1) v += __shfl_down_sync(0xffffffffu, v, o);
    return v;
}
__device__ __forceinline__ float block_reduce(float v, float* red) {
    int t = threadIdx.x;
    red[t] = v;
    __syncthreads();
#pragma unroll
    for (int s = 128; s > 0; s >>= 1) {
        if (t < s) red[t] += red[t + s];
        __syncthreads();
    }
    float r = red[0];
    __syncthreads();
    return r;
}
__device__ __forceinline__ float sigf(float x) { return 1.f / (1.f + expf(-x)); }
__device__ __forceinline__ float to_tf32(float x) {
    float r;
    asm("cvt.rna.tf32.f32 %0, %1;" : "=f"(r) : "f"(x));
    return r;
}

// ---------------- kernel 1: neighbor encoder ----------------
__global__ __launch_bounds__(256) void neighbor_enc_kernel(
    const float* __restrict__ emb, const float* __restrict__ gcn_W,
    const float* __restrict__ gcn_wb, const float* __restrict__ gate_W,
    const float* __restrict__ gate_b, const int* __restrict__ query,
    const int* __restrict__ support, const int* __restrict__ qlc,
    const int* __restrict__ qrc, const int* __restrict__ slc,
    const int* __restrict__ src_, const int* __restrict__ knn_tab)
{
    __shared__ float cs[EE];
    __shared__ float pv[EE];
    __shared__ float sim[NN];
    __shared__ int   entid[NN];
    __shared__ float sim2[KT];
    __shared__ int   kid[KT];
    __shared__ int   selflag[NN];
    __shared__ int   selA[KK], selR[KK], selK[KK];
    __shared__ float cm[2 * EE];
    __shared__ float km[EE];
    __shared__ float strv[EE], knm[EE];
    __shared__ float red[256];
    __shared__ float s_ncc, s_alpha;

    int b = blockIdx.x, t = threadIdx.x;
    int lane = t & 31, warp = t >> 5;

    const int* conn; int eid; float* dst; int row;
    if (b < BQ)                 { row = b;               conn = qlc  + row * NN * 2; eid = query[2 * row];       dst = g_query_n + row * DM; }
    else if (b < 2 * BQ)        { row = b - BQ;          conn = qrc  + row * NN * 2; eid = query[2 * row + 1];   dst = g_query_n + row * DM + EE; }
    else if (b < 2 * BQ + BS)   { row = b - 2 * BQ;      conn = slc  + row * NN * 2; eid = support[2 * row];     dst = g_supp_n  + row * DM; }
    else                        { row = b - 2 * BQ - BS; conn = src_ + row * NN * 2; eid = support[2 * row + 1]; dst = g_supp_n  + row * DM + EE; }
    if (eid < 0 || eid >= VV) eid = PAD_ID;

    if (t < EE) {
        cs[t] = emb[(size_t)eid * EE + t];
        pv[t] = emb[(size_t)PAD_ID * EE + t];
    }
    if (t < KT) {
        int k = knn_tab[(size_t)eid * KT + t];
        if (k < 0 || k >= VV) k = PAD_ID;
        kid[t] = k;
    }
    __syncthreads();

    float p = (t < EE) ? cs[t] * cs[t] : 0.f;
    float csum = block_reduce(p, red);
    if (t == 0) s_ncc = fmaxf(sqrtf(csum), 1e-8f);
    __syncthreads();
    float ncc = s_ncc;

    const float4* emb4 = (const float4*)emb;
    const float4* cs4  = (const float4*)cs;
    float4 c4 = cs4[lane];

    // pass A: 128 structural cos sims; 2 neighbors per warp-iter for MLP
#pragma unroll 1
    for (int it = 0; it < NN / 16; it++) {
        int n0 = it * 16 + warp, n1 = n0 + 8;
        int e0 = conn[2 * n0 + 1], e1 = conn[2 * n1 + 1];
        float4 v0 = emb4[(size_t)e0 * 32 + lane];
        float4 v1 = emb4[(size_t)e1 * 32 + lane];
        float d0 = v0.x * c4.x + v0.y * c4.y + v0.z * c4.z + v0.w * c4.w;
        float q0 = v0.x * v0.x + v0.y * v0.y + v0.z * v0.z + v0.w * v0.w;
        float d1 = v1.x * c4.x + v1.y * c4.y + v1.z * c4.z + v1.w * c4.w;
        float q1 = v1.x * v1.x + v1.y * v1.y + v1.z * v1.z + v1.w * v1.w;
        d0 = warp_sum(d0); q0 = warp_sum(q0);
        d1 = warp_sum(d1); q1 = warp_sum(q1);
        if (lane == 0) {
            sim[n0] = d0 / (fmaxf(sqrtf(q0), 1e-8f) * ncc); entid[n0] = e0;
            sim[n1] = d1 / (fmaxf(sqrtf(q1), 1e-8f) * ncc); entid[n1] = e1;
        }
    }
    __syncthreads();

    // pass B: exact top-32 rank counting
    if (t < NN) {
        float si = sim[t]; int r = 0;
#pragma unroll 8
        for (int j = 0; j < NN; j++) {
            float sj = sim[j];
            r += (sj > si) || (sj == si && j < t);
        }
        selflag[t] = (r < KK) ? 1 : 0;
    }
    __syncthreads();
    if (t < NN && selflag[t]) {
        int pos = 0;
        for (int j = 0; j < t; j++) pos += selflag[j];
        selA[pos] = entid[t];
        selR[pos] = conn[2 * t];
    }
    __syncthreads();

    // pass C
    if (t < EE) {
        float acc = 0.f;
#pragma unroll 4
        for (int s = 0; s < KK; s++) acc += emb[(size_t)selA[s] * EE + t];
        cm[EE + t] = acc * (1.f / KK);
    } else {
        int f = t - EE;
        float acc = 0.f;
#pragma unroll 4
        for (int s = 0; s < KK; s++) acc += emb[(size_t)selR[s] * EE + f];
        cm[f] = acc * (1.f / KK);
    }

    // pass D: knn sims
#pragma unroll 1
    for (int it = 0; it < KT / 16; it++) {
        int n0 = it * 16 + warp, n1 = n0 + 8;
        int e0 = kid[n0], e1 = kid[n1];
        float4 v0 = emb4[(size_t)e0 * 32 + lane];
        float4 v1 = emb4[(size_t)e1 * 32 + lane];
        float d0 = v0.x * c4.x + v0.y * c4.y + v0.z * c4.z + v0.w * c4.w;
        float q0 = v0.x * v0.x + v0.y * v0.y + v0.z * v0.z + v0.w * v0.w;
        float d1 = v1.x * c4.x + v1.y * c4.y + v1.z * c4.z + v1.w * c4.w;
        float q1 = v1.x * v1.x + v1.y * v1.y + v1.z * v1.z + v1.w * v1.w;
        d0 = warp_sum(d0); q0 = warp_sum(q0);
        d1 = warp_sum(d1); q1 = warp_sum(q1);
        if (lane == 0) {
            sim2[n0] = d0 / (fmaxf(sqrtf(q0), 1e-8f) * ncc);
            sim2[n1] = d1 / (fmaxf(sqrtf(q1), 1e-8f) * ncc);
        }
    }
    __syncthreads();
    if (t < KT) {
        float si = sim2[t]; int r = 0;
#pragma unroll 8
        for (int j = 0; j < KT; j++) {
            float sj = sim2[j];
            r += (sj > si) || (sj == si && j < t);
        }
        selflag[t] = (r < KK) ? 1 : 0;
    }
    __syncthreads();
    if (t < KT && selflag[t]) {
        int pos = 0;
        for (int j = 0; j < t; j++) pos += selflag[j];
        selK[pos] = kid[t];
    }
    __syncthreads();
    if (t < EE) {
        float acc = 0.f;
#pragma unroll 4
        for (int s = 0; s < KK; s++) acc += emb[(size_t)selK[s] * EE + t];
        km[t] = acc * (1.f / KK);
    }
    __syncthreads();

    // pass E: GCN matvecs
#pragma unroll 1
    for (int i = 0; i < EE / 8; i++) {
        int e = warp + 8 * i;
        const float* wrow = gcn_W + e * 2 * EE;
        float a1 = 0.f, a2 = 0.f;
#pragma unroll
        for (int jj = 0; jj < 8; jj++) {
            int d = lane + 32 * jj;
            a1 += cm[d] * wrow[d];
        }
#pragma unroll
        for (int jj = 0; jj < 4; jj++) {
            int d = lane + 32 * jj;
            a2 += km[d] * wrow[EE + d] + pv[d] * wrow[d];
        }
        a1 = warp_sum(a1); a2 = warp_sum(a2);
        if (lane == 0) {
            strv[e] = tanhf(a1 + gcn_wb[e]);
            knm[e]  = tanhf(a2 + gcn_wb[e]);
        }
    }
    __syncthreads();

    float gp = (t < EE) ? (strv[t] * gate_W[t] + knm[t] * gate_W[EE + t]) : 0.f;
    float gl = block_reduce(gp, red);
    if (t == 0) s_alpha = sigf(gl + gate_b[0]);
    __syncthreads();
    float a = s_alpha;
    if (t < EE) dst[t] = (1.f - a) * strv[t] + a * knm[t];
}

// ---------------- kernel 2a/2b: support encoder + reduce ----------------
__global__ __launch_bounds__(256) void support_row_kernel(
    const float* __restrict__ se_w1, const float* __restrict__ se_b1,
    const float* __restrict__ se_w2, const float* __restrict__ se_b2,
    const float* __restrict__ ln_g, const float* __restrict__ ln_b)
{
    __shared__ float xs[DM];
    __shared__ float h1s[HHs];
    __shared__ float red[256];
    int r = blockIdx.x, t = threadIdx.x;

    xs[t] = g_supp_n[r * DM + t];
    __syncthreads();

#pragma unroll
    for (int h = 0; h < 2; h++) {
        int n = t + h * 256;
        const float* wr = se_w1 + (size_t)n * DM;
        float acc = 0.f;
        for (int k = 0; k < DM; k++) acc += xs[k] * wr[k];
        h1s[n] = fmaxf(acc + se_b1[n], 0.f);
    }
    __syncthreads();

    const float* wr = se_w2 + (size_t)t * HHs;
    float acc = 0.f;
    for (int k = 0; k < HHs; k++) acc += h1s[k] * wr[k];
    float x = acc + se_b2[t] + xs[t];

    float mu = block_reduce(x, red) * (1.f / DM);
    float dx = x - mu;
    float var = block_reduce(dx * dx, red) * (1.f / DM);
    g_se_supp[r * DM + t] = dx * rsqrtf(var + 1e-5f) * ln_g[t] + ln_b[t];
}

__global__ __launch_bounds__(256) void support_reduce_kernel()
{
    __shared__ float red[256];
    int t = threadIdx.x;
    float s = 0.f;
#pragma unroll
    for (int r = 0; r < BS; r++) s += g_se_supp[r * DM + t];
    float sg = s * (1.f / BS);
    g_support_g[t] = sg;
    float nrm = block_reduce(sg * sg, red);
    if (t == 0) g_sg_norm = fmaxf(sqrtf(nrm), 1e-12f);
}

// ---------------- kernel 3: whh_sg ----------------
__global__ __launch_bounds__(256) void whh_sg_kernel(const float* __restrict__ W_hh)
{
    int warp = threadIdx.x >> 5, lane = threadIdx.x & 31;
    int n = blockIdx.x * 8 + warp;
    const float* wr = W_hh + (size_t)n * HHs + DM;
    float acc = 0.f;
#pragma unroll
    for (int jj = 0; jj < 8; jj++) {
        int j = lane + 32 * jj;
        acc += wr[j] * g_support_g[j];
    }
    acc = warp_sum(acc);
    if (lane == 0) g_whh_sg[n] = acc;
}

// ================= double-buffered tf32 GEMM core macros =================
// smem pool layout (floats): As0 @0, As1 @4352, Bs0 @8704, Bs1 @11008
#define LDSA 136
#define LDSB 72

#define GEMM_STS(bufsel) do {                                                  \
    float* Asb = pool + (bufsel) * 4352;                                       \
    float* Bsb = pool + 8704 + (bufsel) * 2304;                                \
    _Pragma("unroll")                                                          \
    for (int i = 0; i < 4; i++) {                                              \
        int k = ac + i * 4;                                                    \
        Asb[(k + 0) * LDSA + ar] = to_tf32(aReg[i].x);                         \
        Asb[(k + 1) * LDSA + ar] = to_tf32(aReg[i].y);                         \
        Asb[(k + 2) * LDSA + ar] = to_tf32(aReg[i].z);                         \
        Asb[(k + 3) * LDSA + ar] = to_tf32(aReg[i].w);                         \
    }                                                                          \
    _Pragma("unroll")                                                          \
    for (int i = 0; i < 2; i++) {                                              \
        int k = bc + i * 4;                                                    \
        Bsb[(k + 0) * LDSB + br] = to_tf32(bReg[i].x);                         \
        Bsb[(k + 1) * LDSB + br] = to_tf32(bReg[i].y);                         \
        Bsb[(k + 2) * LDSB + br] = to_tf32(bReg[i].z);                         \
        Bsb[(k + 3) * LDSB + br] = to_tf32(bReg[i].w);                         \
    }                                                                          \
} while (0)

#define GEMM_LDG(off) do {                                                     \
    _Pragma("unroll")                                                          \
    for (int i = 0; i < 4; i++) aReg[i] = *(const float4*)(Aptr + (off) + i * 4); \
    _Pragma("unroll")                                                          \
    for (int i = 0; i < 2; i++) bReg[i] = *(const float4*)(Bptr + (off) + i * 4); \
} while (0)

#define GEMM_COMPUTE(bufsel) do {                                              \
    const float* Asb = pool + (bufsel) * 4352;                                 \
    const float* Bsb = pool + 8704 + (bufsel) * 2304;                          \
    _Pragma("unroll")                                                          \
    for (int k0 = 0; k0 < 32; k0 += 8) {                                       \
        unsigned a[2][4], bfr[4][2];                                           \
        _Pragma("unroll")                                                      \
        for (int mt = 0; mt < 2; mt++) {                                       \
            int m = wm + mt * 16 + r0;                                         \
            a[mt][0] = __float_as_uint(Asb[(k0 + q) * LDSA + m]);              \
            a[mt][1] = __float_as_uint(Asb[(k0 + q) * LDSA + m + 8]);          \
            a[mt][2] = __float_as_uint(Asb[(k0 + q + 4) * LDSA + m]);          \
            a[mt][3] = __float_as_uint(Asb[(k0 + q + 4) * LDSA + m + 8]);      \
        }                                                                      \
        _Pragma("unroll")                                                      \
        for (int nt = 0; nt < 4; nt++) {                                       \
            int n = wn + nt * 8 + r0;                                          \
            bfr[nt][0] = __float_as_uint(Bsb[(k0 + q) * LDSB + n]);            \
            bfr[nt][1] = __float_as_uint(Bsb[(k0 + q + 4) * LDSB + n]);        \
        }                                                                      \
        _Pragma("unroll")                                                      \
        for (int mt = 0; mt < 2; mt++)                                         \
            _Pragma("unroll")                                                  \
            for (int nt = 0; nt < 4; nt++) {                                   \
                asm volatile(                                                  \
                    "mma.sync.aligned.m16n8k8.row.col.f32.tf32.tf32.f32 "      \
                    "{%0,%1,%2,%3}, {%4,%5,%6,%7}, {%8,%9}, {%0,%1,%2,%3};"    \
                    : "+f"(c[mt][nt][0]), "+f"(c[mt][nt][1]),                  \
                      "+f"(c[mt][nt][2]), "+f"(c[mt][nt][3])                   \
                    : "r"(a[mt][0]), "r"(a[mt][1]), "r"(a[mt][2]), "r"(a[mt][3]), \
                      "r"(bfr[nt][0]), "r"(bfr[nt][1]));                       \
            }                                                                  \
    }                                                                          \
} while (0)

// ---------------- generic tf32 GEMM: C = A @ B^T (+ epilogue) ----------------
// mode 1: relu(+bias) | 2: +bias +add | 3: +bias +bias2
__global__ __launch_bounds__(256) void tf32_gemm_nt(
    const float* __restrict__ A, int lda, const float* __restrict__ B, int ldb,
    float* __restrict__ C, int M, int N, int K, int mode,
    const float* __restrict__ bias, const float* __restrict__ bias2,
    const float* __restrict__ add)
{
    extern __shared__ float pool[];
    int tid = threadIdx.x, lane = tid & 31, wid = tid >> 5;
    int bm = blockIdx.y * 128, bn = blockIdx.x * 64;
    int wm = (wid >> 1) * 32, wn = (wid & 1) * 32;
    int r0 = lane >> 2, q = lane & 3;

    float c[2][4][4];
#pragma unroll
    for (int mt = 0; mt < 2; mt++)
#pragma unroll
        for (int nt = 0; nt < 4; nt++)
#pragma unroll
            for (int i = 0; i < 4; i++) c[mt][nt][i] = 0.f;

    int ar = tid >> 1, ac = (tid & 1) * 16;
    int br = tid >> 2, bc = (tid & 3) * 8;
    const float* Aptr = A + (size_t)(bm + ar) * lda + ac;
    const float* Bptr = B + (size_t)(bn + br) * ldb + bc;

    float4 aReg[4]; float4 bReg[2];
    GEMM_LDG(0);
    GEMM_STS(0);
    __syncthreads();

    int nb = K / 32;
    for (int it = 0; it < nb; it++) {
        int buf = it & 1;
        if (it + 1 < nb) GEMM_LDG((it + 1) * 32);
        GEMM_COMPUTE(buf);
        if (it + 1 < nb) GEMM_STS(buf ^ 1);
        __syncthreads();
    }

#pragma unroll
    for (int mt = 0; mt < 2; mt++) {
        int mrow = bm + wm + mt * 16 + r0;
#pragma unroll
        for (int nt = 0; nt < 4; nt++) {
            int ncol = bn + wn + nt * 8 + 2 * q;
#pragma unroll
            for (int i = 0; i < 4; i++) {
                int m = mrow + (i >> 1) * 8;
                int n = ncol + (i & 1);
                float v = c[mt][nt][i];
                if (mode == 1)      v = fmaxf(v + bias[n], 0.f);
                else if (mode == 2) v = v + bias[n] + add[(size_t)m * N + n];
                else if (mode == 3) v = v + bias[n] + bias2[n];
                C[(size_t)m * N + n] = v;
            }
        }
    }
}

// ---------------- fused LSTM step: GEMM + gates + cell, gate-interleaved B ----------------
// Block (tb, bm): j in [tb*16, tb*16+16), all 4 gates. hin: [BQ,256], W_hh ldb=512.
__global__ __launch_bounds__(256) void lstm_step_fused(
    const float* __restrict__ hin, const float* __restrict__ W_hh,
    float* __restrict__ hout)
{
    extern __shared__ float pool[];
    __shared__ float wsh[64];
    int tid = threadIdx.x, lane = tid & 31, wid = tid >> 5;
    int tb = blockIdx.x;
    int bm = blockIdx.y * 128;
    int wm = (wid >> 1) * 32, wn = (wid & 1) * 32;
    int r0 = lane >> 2, q = lane & 3;

    float c[2][4][4];
#pragma unroll
    for (int mt = 0; mt < 2; mt++)
#pragma unroll
        for (int nt = 0; nt < 4; nt++)
#pragma unroll
            for (int i = 0; i < 4; i++) c[mt][nt][i] = 0.f;

    int ar = tid >> 1, ac = (tid & 1) * 16;
    int br = tid >> 2, bc = (tid & 3) * 8;
    const float* Aptr = hin + (size_t)(bm + ar) * DM + ac;
    int brow = (br >> 4) * 512 + tb * 16 + (br & 15);
    const float* Bptr = W_hh + (size_t)brow * HHs + bc;

    if (tid < 64) wsh[tid] = g_whh_sg[(tid >> 4) * 512 + tb * 16 + (tid & 15)];

    float4 aReg[4]; float4 bReg[2];
    GEMM_LDG(0);
    GEMM_STS(0);
    __syncthreads();

    const int nb = DM / 32;   // 8
#pragma unroll 1
    for (int it = 0; it < nb; it++) {
        int buf = it & 1;
        if (it + 1 < nb) GEMM_LDG((it + 1) * 32);
        GEMM_COMPUTE(buf);
        if (it + 1 < nb) GEMM_STS(buf ^ 1);
        __syncthreads();
    }

    // exchange fragments through smem (alias pool; mainloop done, sync'd)
    float* Cs = pool;   // 128 x 68
#pragma unroll
    for (int mt = 0; mt < 2; mt++) {
        int mrow = wm + mt * 16 + r0;
#pragma unroll
        for (int nt = 0; nt < 4; nt++) {
            int ncol = wn + nt * 8 + 2 * q;
#pragma unroll
            for (int i = 0; i < 4; i++) {
                int m = mrow + (i >> 1) * 8;
                int l = ncol + (i & 1);
                Cs[m * 68 + l] = c[mt][nt][i];
            }
        }
    }
    __syncthreads();

    // gates + cell update: 2048 outputs, 8 per thread
    const float* zq = g_zq;
#pragma unroll
    for (int ii = 0; ii < 8; ii++) {
        int o = ii * 256 + tid;
        int m = o >> 4, jl = o & 15;
        int grow = bm + m;
        int jg = tb * 16 + jl;
        const float* zr = zq + (size_t)grow * G4 + jg;
        float iv = Cs[m * 68 + jl]      + zr[0]    + wsh[jl];
        float fv = Cs[m * 68 + 16 + jl] + zr[512]  + wsh[16 + jl];
        float gv = Cs[m * 68 + 32 + jl] + zr[1024] + wsh[32 + jl];
        float ov = Cs[m * 68 + 48 + jl] + zr[1536] + wsh[48 + jl];
        float cp = g_c[grow * HHs + jg];
        float c2 = sigf(fv) * cp + sigf(iv) * tanhf(gv);
        g_c[grow * HHs + jg] = c2;
        if (jg < DM)
            hout[grow * DM + jg] = g_query_g[grow * DM + jg] + sigf(ov) * tanhf(c2);
    }
}

// ---------------- LayerNorm ----------------
__global__ __launch_bounds__(256) void ln_kernel(const float* __restrict__ ln_g,
                                                 const float* __restrict__ ln_b)
{
    __shared__ float red[256];
    int m = blockIdx.x, t = threadIdx.x;
    float x = g_hpre[m * DM + t];
    float mu = block_reduce(x, red) * (1.f / DM);
    float dx = x - mu;
    float var = block_reduce(dx * dx, red) * (1.f / DM);
    g_query_g[m * DM + t] = dx * rsqrtf(var + 1e-5f) * ln_g[t] + ln_b[t];
}

// ---------------- LSTM step 1 (h_r = 0 -> z = zq) ----------------
__global__ __launch_bounds__(256) void lstm_cell_first(float* __restrict__ hout)
{
    int idx = blockIdx.x * 256 + threadIdx.x;
    int m = idx >> 9, j = idx & 511;
    const float* zr = g_zq + (size_t)m * G4;
    float iv = zr[j], gv = zr[1024 + j], ov = zr[1536 + j];
    float c2 = sigf(iv) * tanhf(gv);   // c_prev = 0
    g_c[idx] = c2;
    if (j < DM) {
        float h2 = sigf(ov) * tanhf(c2);
        hout[m * DM + j] = g_query_g[m * DM + j] + h2;
    }
}

// ---------------- final cosine score ----------------
__global__ __launch_bounds__(256) void final_kernel(const float* __restrict__ h,
                                                    float* __restrict__ out)
{
    int warp = threadIdx.x >> 5, lane = threadIdx.x & 31;
    int m = blockIdx.x * 8 + warp;
    float d = 0.f, hh = 0.f;
#pragma unroll
    for (int jj = 0; jj < 8; jj++) {
        int j = lane + 32 * jj;
        float hv = h[m * DM + j];
        d += hv * g_support_g[j];
        hh += hv * hv;
    }
    d = warp_sum(d); hh = warp_sum(hh);
    if (lane == 0) out[m] = d / (fmaxf(sqrtf(hh), 1e-12f) * g_sg_norm);
}

// ---------------- launch ----------------
extern "C" void kernel_launch(void* const* d_in, const int* in_sizes, int n_in,
                              void* d_out, int out_size)
{
    const float* emb     = (const float*)d_in[0];
    const float* gcn_W   = (const float*)d_in[1];
    const float* gcn_wb  = (const float*)d_in[2];
    const float* gate_W  = (const float*)d_in[3];
    const float* gate_b  = (const float*)d_in[4];
    const float* se_w1   = (const float*)d_in[5];
    const float* se_b1   = (const float*)d_in[6];
    const float* se_w2   = (const float*)d_in[7];
    const float* se_b2   = (const float*)d_in[8];
    const float* ln_g    = (const float*)d_in[9];
    const float* ln_b    = (const float*)d_in[10];
    const float* W_ih    = (const float*)d_in[11];
    const float* W_hh    = (const float*)d_in[12];
    const float* b_ih    = (const float*)d_in[13];
    const float* b_hh    = (const float*)d_in[14];
    const int*   query   = (const int*)d_in[15];
    const int*   support = (const int*)d_in[16];
    const int*   qlc     = (const int*)d_in[17];
    const int*   qrc     = (const int*)d_in[19];
    const int*   slc     = (const int*)d_in[21];
    const int*   src_    = (const int*)d_in[23];
    const int*   knn_tab = (const int*)d_in[25];
    float* out = (float*)d_out;

    float *p_qn, *p_qg, *p_h1, *p_hpre, *p_zq, *p_hA, *p_hB;
    cudaGetSymbolAddress((void**)&p_qn,   g_query_n);
    cudaGetSymbolAddress((void**)&p_qg,   g_query_g);
    cudaGetSymbolAddress((void**)&p_h1,   g_h1);
    cudaGetSymbolAddress((void**)&p_hpre, g_hpre);
    cudaGetSymbolAddress((void**)&p_zq,   g_zq);
    cudaGetSymbolAddress((void**)&p_hA,   g_hA);
    cudaGetSymbolAddress((void**)&p_hB,   g_hB);

    static int attr_done = 0;
    if (!attr_done) {
        cudaFuncSetAttribute(tf32_gemm_nt, cudaFuncAttributeMaxDynamicSharedMemorySize, GEMM_SMEM_BYTES);
        cudaFuncSetAttribute(lstm_step_fused, cudaFuncAttributeMaxDynamicSharedMemorySize, GEMM_SMEM_BYTES);
        attr_done = 1;
    }

    // 1. neighbor encoders
    neighbor_enc_kernel<<<2 * BQ + 2 * BS, 256>>>(emb, gcn_W, gcn_wb, gate_W, gate_b,
                                                  query, support, qlc, qrc, slc, src_, knn_tab);
    // 2. support SE + reduce
    support_row_kernel<<<BS, 256>>>(se_w1, se_b1, se_w2, se_b2, ln_g, ln_b);
    support_reduce_kernel<<<1, 256>>>();
    // 3. support recurrent term
    whh_sg_kernel<<<G4 / 8, 256>>>(W_hh);

    // 4. query SE
    {
        dim3 g1(HHs / 64, BQ / 128);
        tf32_gemm_nt<<<g1, 256, GEMM_SMEM_BYTES>>>(p_qn, DM, se_w1, DM, p_h1, BQ, HHs, DM, 1, se_b1, nullptr, nullptr);
        dim3 g2(DM / 64, BQ / 128);
        tf32_gemm_nt<<<g2, 256, GEMM_SMEM_BYTES>>>(p_h1, HHs, se_w2, HHs, p_hpre, BQ, DM, HHs, 2, se_b2, nullptr, p_qn);
        ln_kernel<<<BQ, 256>>>(ln_g, ln_b);
    }

    // 5. zq = query_g @ W_ih^T + b_ih + b_hh
    dim3 g3(G4 / 64, BQ / 128);
    tf32_gemm_nt<<<g3, 256, GEMM_SMEM_BYTES>>>(p_qg, DM, W_ih, DM, p_zq, BQ, G4, DM, 3, b_ih, b_hh, nullptr);

    // 6. step 1 (no GEMM), h -> hA
    lstm_cell_first<<<(BQ * HHs) / 256, 256>>>(p_hA);

    // 7. steps 2..4: fused GEMM + cell, ping-pong h buffers
    dim3 gf(HHs / 16, BQ / 128);   // (32, 16)
    lstm_step_fused<<<gf, 256, GEMM_SMEM_BYTES>>>(p_hA, W_hh, p_hB);
    lstm_step_fused<<<gf, 256, GEMM_SMEM_BYTES>>>(p_hB, W_hh, p_hA);
    lstm_step_fused<<<gf, 256, GEMM_SMEM_BYTES>>>(p_hA, W_hh, p_hB);

    // 8. cosine score
    final_kernel<<<BQ / 8, 256>>>(p_hB, out);
}

// round 5
// speedup vs baseline: 1.5711x; 1.1049x over previous
#include <cuda_runtime.h>
#include <math.h>
#include <stdint.h>

#define VV      200000
#define EE      128
#define PAD_ID  199999
#define KK      32
#define BQ      2048
#define BS      5
#define NN      128
#define KT      64
#define DM      256
#define HHs     512
#define G4      2048

// smem sizes (bytes)
#define GEMM128_SMEM 73728   // 2*(128*36 + 128*36)*4
#define GEMM64_SMEM  55296   // 2*(128*36 + 64*36)*4

// ---------------- scratch ----------------
__device__ float g_query_n[BQ * DM];
__device__ float g_supp_n[BS * DM];
__device__ float g_se_supp[BS * DM];
__device__ float g_query_g[BQ * DM];
__device__ float g_h1[BQ * HHs];
__device__ float g_hpre[BQ * DM];
__device__ float g_support_g[DM];
__device__ float g_sg_norm;
__device__ float g_whh_sg[G4];
__device__ float g_zq[(size_t)BQ * G4];
__device__ float g_hA[BQ * DM];
__device__ float g_hB[BQ * DM];
__device__ float g_c[BQ * HHs];

// ---------------- helpers ----------------
__device__ __forceinline__ float warp_sum(float v) {
#pragma unroll
    for (int o = 16; o; o >>= 1) v += __shfl_down_sync(0xffffffffu, v, o);
    return v;
}
__device__ __forceinline__ float block_reduce(float v, float* red) {
    int t = threadIdx.x;
    red[t] = v;
    __syncthreads();
#pragma unroll
    for (int s = 128; s > 0; s >>= 1) {
        if (t < s) red[t] += red[t + s];
        __syncthreads();
    }
    float r = red[0];
    __syncthreads();
    return r;
}
__device__ __forceinline__ float sigf(float x) { return 1.f / (1.f + expf(-x)); }
__device__ __forceinline__ uint32_t smem_u32(const void* p) {
    return (uint32_t)__cvta_generic_to_shared(p);
}
__device__ __forceinline__ void cp_async16(uint32_t s, const void* g) {
    asm volatile("cp.async.ca.shared.global [%0], [%1], 16;" :: "r"(s), "l"(g));
}
__device__ __forceinline__ void cp_commit() { asm volatile("cp.async.commit_group;"); }
__device__ __forceinline__ void cp_wait1() { asm volatile("cp.async.wait_group 1;"); }

#define MMA_TF32(cc, a0, a1, a2, a3, b0, b1)                                   \
    asm volatile(                                                              \
        "mma.sync.aligned.m16n8k8.row.col.f32.tf32.tf32.f32 "                  \
        "{%0,%1,%2,%3}, {%4,%5,%6,%7}, {%8,%9}, {%0,%1,%2,%3};"                \
        : "+f"((cc)[0]), "+f"((cc)[1]), "+f"((cc)[2]), "+f"((cc)[3])           \
        : "r"(a0), "r"(a1), "r"(a2), "r"(a3), "r"(b0), "r"(b1))

// ---------------- kernel 1: neighbor encoder (one block per row-side) ----------------
__global__ __launch_bounds__(256) void neighbor_enc_kernel(
    const float* __restrict__ emb, const float* __restrict__ gcn_W,
    const float* __restrict__ gcn_wb, const float* __restrict__ gate_W,
    const float* __restrict__ gate_b, const int* __restrict__ query,
    const int* __restrict__ support, const int* __restrict__ qlc,
    const int* __restrict__ qrc, const int* __restrict__ slc,
    const int* __restrict__ src_, const int* __restrict__ knn_tab, int base)
{
    __shared__ float cs[EE];
    __shared__ float pv[EE];
    __shared__ float sim[NN];
    __shared__ int   entid[NN];
    __shared__ float sim2[KT];
    __shared__ int   kid[KT];
    __shared__ int   selflag[NN];
    __shared__ int   selA[KK], selR[KK], selK[KK];
    __shared__ float cm[2 * EE];
    __shared__ float km[EE];
    __shared__ float strv[EE], knm[EE];
    __shared__ float red[256];
    __shared__ float s_ncc, s_alpha;

    int b = blockIdx.x + base, t = threadIdx.x;
    int lane = t & 31, warp = t >> 5;

    const int* conn; int eid; float* dst; int row;
    if (b < BQ)                 { row = b;               conn = qlc  + row * NN * 2; eid = query[2 * row];       dst = g_query_n + row * DM; }
    else if (b < 2 * BQ)        { row = b - BQ;          conn = qrc  + row * NN * 2; eid = query[2 * row + 1];   dst = g_query_n + row * DM + EE; }
    else if (b < 2 * BQ + BS)   { row = b - 2 * BQ;      conn = slc  + row * NN * 2; eid = support[2 * row];     dst = g_supp_n  + row * DM; }
    else                        { row = b - 2 * BQ - BS; conn = src_ + row * NN * 2; eid = support[2 * row + 1]; dst = g_supp_n  + row * DM + EE; }
    if (eid < 0 || eid >= VV) eid = PAD_ID;

    if (t < EE) {
        cs[t] = emb[(size_t)eid * EE + t];
        pv[t] = emb[(size_t)PAD_ID * EE + t];
    }
    if (t < KT) {
        int k = knn_tab[(size_t)eid * KT + t];
        if (k < 0 || k >= VV) k = PAD_ID;
        kid[t] = k;
    }
    __syncthreads();

    float p = (t < EE) ? cs[t] * cs[t] : 0.f;
    float csum = block_reduce(p, red);
    if (t == 0) s_ncc = fmaxf(sqrtf(csum), 1e-8f);
    __syncthreads();
    float ncc = s_ncc;

    const float4* emb4 = (const float4*)emb;
    const float4* cs4  = (const float4*)cs;
    float4 c4 = cs4[lane];

    // pass A: 128 structural cos sims; 2 neighbors per warp-iter
#pragma unroll 1
    for (int it = 0; it < NN / 16; it++) {
        int n0 = it * 16 + warp, n1 = n0 + 8;
        int e0 = conn[2 * n0 + 1], e1 = conn[2 * n1 + 1];
        float4 v0 = emb4[(size_t)e0 * 32 + lane];
        float4 v1 = emb4[(size_t)e1 * 32 + lane];
        float d0 = v0.x * c4.x + v0.y * c4.y + v0.z * c4.z + v0.w * c4.w;
        float q0 = v0.x * v0.x + v0.y * v0.y + v0.z * v0.z + v0.w * v0.w;
        float d1 = v1.x * c4.x + v1.y * c4.y + v1.z * c4.z + v1.w * c4.w;
        float q1 = v1.x * v1.x + v1.y * v1.y + v1.z * v1.z + v1.w * v1.w;
        d0 = warp_sum(d0); q0 = warp_sum(q0);
        d1 = warp_sum(d1); q1 = warp_sum(q1);
        if (lane == 0) {
            sim[n0] = d0 / (fmaxf(sqrtf(q0), 1e-8f) * ncc); entid[n0] = e0;
            sim[n1] = d1 / (fmaxf(sqrtf(q1), 1e-8f) * ncc); entid[n1] = e1;
        }
    }
    __syncthreads();

    // pass B: exact top-32 rank counting (matches lax.top_k tie-break)
    if (t < NN) {
        float si = sim[t]; int r = 0;
#pragma unroll 8
        for (int j = 0; j < NN; j++) {
            float sj = sim[j];
            r += (sj > si) || (sj == si && j < t);
        }
        selflag[t] = (r < KK) ? 1 : 0;
    }
    __syncthreads();
    if (t < NN && selflag[t]) {
        int pos = 0;
        for (int j = 0; j < t; j++) pos += selflag[j];
        selA[pos] = entid[t];
        selR[pos] = conn[2 * t];
    }
    __syncthreads();

    // pass C: rel/ent means
    if (t < EE) {
        float acc = 0.f;
#pragma unroll 4
        for (int s = 0; s < KK; s++) acc += emb[(size_t)selA[s] * EE + t];
        cm[EE + t] = acc * (1.f / KK);
    } else {
        int f = t - EE;
        float acc = 0.f;
#pragma unroll 4
        for (int s = 0; s < KK; s++) acc += emb[(size_t)selR[s] * EE + f];
        cm[f] = acc * (1.f / KK);
    }

    // pass D: knn sims
#pragma unroll 1
    for (int it = 0; it < KT / 16; it++) {
        int n0 = it * 16 + warp, n1 = n0 + 8;
        int e0 = kid[n0], e1 = kid[n1];
        float4 v0 = emb4[(size_t)e0 * 32 + lane];
        float4 v1 = emb4[(size_t)e1 * 32 + lane];
        float d0 = v0.x * c4.x + v0.y * c4.y + v0.z * c4.z + v0.w * c4.w;
        float q0 = v0.x * v0.x + v0.y * v0.y + v0.z * v0.z + v0.w * v0.w;
        float d1 = v1.x * c4.x + v1.y * c4.y + v1.z * c4.z + v1.w * c4.w;
        float q1 = v1.x * v1.x + v1.y * v1.y + v1.z * v1.z + v1.w * v1.w;
        d0 = warp_sum(d0); q0 = warp_sum(q0);
        d1 = warp_sum(d1); q1 = warp_sum(q1);
        if (lane == 0) {
            sim2[n0] = d0 / (fmaxf(sqrtf(q0), 1e-8f) * ncc);
            sim2[n1] = d1 / (fmaxf(sqrtf(q1), 1e-8f) * ncc);
        }
    }
    __syncthreads();
    if (t < KT) {
        float si = sim2[t]; int r = 0;
#pragma unroll 8
        for (int j = 0; j < KT; j++) {
            float sj = sim2[j];
            r += (sj > si) || (sj == si && j < t);
        }
        selflag[t] = (r < KK) ? 1 : 0;
    }
    __syncthreads();
    if (t < KT && selflag[t]) {
        int pos = 0;
        for (int j = 0; j < t; j++) pos += selflag[j];
        selK[pos] = kid[t];
    }
    __syncthreads();
    if (t < EE) {
        float acc = 0.f;
#pragma unroll 4
        for (int s = 0; s < KK; s++) acc += emb[(size_t)selK[s] * EE + t];
        km[t] = acc * (1.f / KK);
    }
    __syncthreads();

    // pass E: GCN matvecs
#pragma unroll 1
    for (int i = 0; i < EE / 8; i++) {
        int e = warp + 8 * i;
        const float* wrow = gcn_W + e * 2 * EE;
        float a1 = 0.f, a2 = 0.f;
#pragma unroll
        for (int jj = 0; jj < 8; jj++) {
            int d = lane + 32 * jj;
            a1 += cm[d] * wrow[d];
        }
#pragma unroll
        for (int jj = 0; jj < 4; jj++) {
            int d = lane + 32 * jj;
            a2 += km[d] * wrow[EE + d] + pv[d] * wrow[d];
        }
        a1 = warp_sum(a1); a2 = warp_sum(a2);
        if (lane == 0) {
            strv[e] = tanhf(a1 + gcn_wb[e]);
            knm[e]  = tanhf(a2 + gcn_wb[e]);
        }
    }
    __syncthreads();

    float gp = (t < EE) ? (strv[t] * gate_W[t] + knm[t] * gate_W[EE + t]) : 0.f;
    float gl = block_reduce(gp, red);
    if (t == 0) s_alpha = sigf(gl + gate_b[0]);
    __syncthreads();
    float a = s_alpha;
    if (t < EE) dst[t] = (1.f - a) * strv[t] + a * knm[t];
}

// ---------------- support encoder + reduce + whh_sg ----------------
__global__ __launch_bounds__(256) void support_row_kernel(
    const float* __restrict__ se_w1, const float* __restrict__ se_b1,
    const float* __restrict__ se_w2, const float* __restrict__ se_b2,
    const float* __restrict__ ln_g, const float* __restrict__ ln_b)
{
    __shared__ float xs[DM];
    __shared__ float h1s[HHs];
    __shared__ float red[256];
    int r = blockIdx.x, t = threadIdx.x;

    xs[t] = g_supp_n[r * DM + t];
    __syncthreads();

#pragma unroll
    for (int h = 0; h < 2; h++) {
        int n = t + h * 256;
        const float* wr = se_w1 + (size_t)n * DM;
        float acc = 0.f;
        for (int k = 0; k < DM; k++) acc += xs[k] * wr[k];
        h1s[n] = fmaxf(acc + se_b1[n], 0.f);
    }
    __syncthreads();

    const float* wr = se_w2 + (size_t)t * HHs;
    float acc = 0.f;
    for (int k = 0; k < HHs; k++) acc += h1s[k] * wr[k];
    float x = acc + se_b2[t] + xs[t];

    float mu = block_reduce(x, red) * (1.f / DM);
    float dx = x - mu;
    float var = block_reduce(dx * dx, red) * (1.f / DM);
    g_se_supp[r * DM + t] = dx * rsqrtf(var + 1e-5f) * ln_g[t] + ln_b[t];
}

__global__ __launch_bounds__(256) void support_reduce_kernel()
{
    __shared__ float red[256];
    int t = threadIdx.x;
    float s = 0.f;
#pragma unroll
    for (int r = 0; r < BS; r++) s += g_se_supp[r * DM + t];
    float sg = s * (1.f / BS);
    g_support_g[t] = sg;
    float nrm = block_reduce(sg * sg, red);
    if (t == 0) g_sg_norm = fmaxf(sqrtf(nrm), 1e-12f);
}

__global__ __launch_bounds__(256) void whh_sg_kernel(const float* __restrict__ W_hh)
{
    int warp = threadIdx.x >> 5, lane = threadIdx.x & 31;
    int n = blockIdx.x * 8 + warp;
    const float* wr = W_hh + (size_t)n * HHs + DM;
    float acc = 0.f;
#pragma unroll
    for (int jj = 0; jj < 8; jj++) {
        int j = lane + 32 * jj;
        acc += wr[j] * g_support_g[j];
    }
    acc = warp_sum(acc);
    if (lane == 0) g_whh_sg[n] = acc;
}

// ================= cp.async tf32 GEMM (raw fp32 -> HW tf32 truncation) =================
// C[m,n] = sum_k A[m,k]*B[n,k]; modes: 1 relu(+bias) | 2 +bias+add | 3 +bias+bias2
// BM=128, BK=32, BN template (64 or 128). smem row-major, pad 36 floats.
template<int BN, int MODE>
__global__ __launch_bounds__(256) void tf32_gemm_cp(
    const float* __restrict__ A, int lda, const float* __restrict__ B, int ldb,
    float* __restrict__ C, int M, int N, int K,
    const float* __restrict__ bias, const float* __restrict__ bias2,
    const float* __restrict__ add)
{
    constexpr int NT = BN / 16;
    constexpr int ASTG = 128 * 36;
    constexpr int BSTG = BN * 36;
    extern __shared__ float pool[];
    float* Ab = pool;
    float* Bb = pool + 2 * ASTG;

    int tid = threadIdx.x, lane = tid & 31, wid = tid >> 5;
    int bm = blockIdx.y * 128, bn = blockIdx.x * BN;
    int wm = (wid >> 1) * 32, wn = (wid & 1) * (BN / 2);
    int r0 = lane >> 2, q = lane & 3;

    float c[2][NT][4];
#pragma unroll
    for (int mt = 0; mt < 2; mt++)
#pragma unroll
        for (int nt = 0; nt < NT; nt++)
#pragma unroll
            for (int i = 0; i < 4; i++) c[mt][nt][i] = 0.f;

    auto copy_tile = [&](int kt, int stage) {
        float* As = Ab + stage * ASTG;
        float* Bs = Bb + stage * BSTG;
#pragma unroll
        for (int i = 0; i < 4; i++) {
            int ci = i * 256 + tid;
            int row = ci >> 3, c4 = (ci & 7) * 4;
            cp_async16(smem_u32(As + row * 36 + c4),
                       A + (size_t)(bm + row) * lda + kt + c4);
        }
#pragma unroll
        for (int i = 0; i < BN / 32; i++) {
            int ci = i * 256 + tid;
            int row = ci >> 3, c4 = (ci & 7) * 4;
            cp_async16(smem_u32(Bs + row * 36 + c4),
                       B + (size_t)(bn + row) * ldb + kt + c4);
        }
        cp_commit();
    };

    auto compute = [&](int stage) {
        const float* As = Ab + stage * ASTG;
        const float* Bs = Bb + stage * BSTG;
#pragma unroll
        for (int k0 = 0; k0 < 32; k0 += 8) {
            unsigned a[2][4];
#pragma unroll
            for (int mt = 0; mt < 2; mt++) {
                int m = wm + mt * 16 + r0;
                a[mt][0] = __float_as_uint(As[m * 36 + k0 + q]);
                a[mt][1] = __float_as_uint(As[(m + 8) * 36 + k0 + q]);
                a[mt][2] = __float_as_uint(As[m * 36 + k0 + q + 4]);
                a[mt][3] = __float_as_uint(As[(m + 8) * 36 + k0 + q + 4]);
            }
#pragma unroll
            for (int nt = 0; nt < NT; nt++) {
                int n = wn + nt * 8 + r0;
                unsigned b0 = __float_as_uint(Bs[n * 36 + k0 + q]);
                unsigned b1 = __float_as_uint(Bs[n * 36 + k0 + q + 4]);
#pragma unroll
                for (int mt = 0; mt < 2; mt++)
                    MMA_TF32(c[mt][nt], a[mt][0], a[mt][1], a[mt][2], a[mt][3], b0, b1);
            }
        }
    };

    int nb = K / 32;
    copy_tile(0, 0);
    if (nb > 1) copy_tile(32, 1); else cp_commit();

#pragma unroll 1
    for (int it = 0; it < nb; it++) {
        cp_wait1();
        __syncthreads();
        compute(it & 1);
        __syncthreads();
        if (it + 2 < nb) copy_tile((it + 2) * 32, it & 1); else cp_commit();
    }

#pragma unroll
    for (int mt = 0; mt < 2; mt++) {
        int mrow = bm + wm + mt * 16 + r0;
#pragma unroll
        for (int nt = 0; nt < NT; nt++) {
            int ncol = bn + wn + nt * 8 + 2 * q;
#pragma unroll
            for (int i = 0; i < 4; i++) {
                int m = mrow + (i >> 1) * 8;
                int n = ncol + (i & 1);
                float v = c[mt][nt][i];
                if (MODE == 1)      v = fmaxf(v + bias[n], 0.f);
                else if (MODE == 2) v = v + bias[n] + add[(size_t)m * N + n];
                else if (MODE == 3) v = v + bias[n] + bias2[n];
                C[(size_t)m * N + n] = v;
            }
        }
    }
}

// ---------------- fused LSTM step: cp.async GEMM + gates + cell ----------------
// Block (tb, bm): j in [tb*16,tb*16+16), all 4 gates (64 B-rows, gate-interleaved).
__global__ __launch_bounds__(256) void lstm_step_fused(
    const float* __restrict__ hin, const float* __restrict__ W_hh,
    float* __restrict__ hout)
{
    constexpr int ASTG = 128 * 36;
    constexpr int BSTG = 64 * 36;
    extern __shared__ float pool[];
    __shared__ float wsh[64];
    float* Ab = pool;
    float* Bb = pool + 2 * ASTG;

    int tid = threadIdx.x, lane = tid & 31, wid = tid >> 5;
    int tb = blockIdx.x;
    int bm = blockIdx.y * 128;
    int wm = (wid >> 1) * 32, wn = (wid & 1) * 32;
    int r0 = lane >> 2, q = lane & 3;

    float c[2][4][4];
#pragma unroll
    for (int mt = 0; mt < 2; mt++)
#pragma unroll
        for (int nt = 0; nt < 4; nt++)
#pragma unroll
            for (int i = 0; i < 4; i++) c[mt][nt][i] = 0.f;

    if (tid < 64) wsh[tid] = g_whh_sg[(tid >> 4) * 512 + tb * 16 + (tid & 15)];

    auto copy_tile = [&](int kt, int stage) {
        float* As = Ab + stage * ASTG;
        float* Bs = Bb + stage * BSTG;
#pragma unroll
        for (int i = 0; i < 4; i++) {
            int ci = i * 256 + tid;
            int row = ci >> 3, c4 = (ci & 7) * 4;
            cp_async16(smem_u32(As + row * 36 + c4),
                       hin + (size_t)(bm + row) * DM + kt + c4);
        }
#pragma unroll
        for (int i = 0; i < 2; i++) {
            int ci = i * 256 + tid;
            int row = ci >> 3, c4 = (ci & 7) * 4;
            int grow = (row >> 4) * 512 + tb * 16 + (row & 15);
            cp_async16(smem_u32(Bs + row * 36 + c4),
                       W_hh + (size_t)grow * HHs + kt + c4);
        }
        cp_commit();
    };

    auto compute = [&](int stage) {
        const float* As = Ab + stage * ASTG;
        const float* Bs = Bb + stage * BSTG;
#pragma unroll
        for (int k0 = 0; k0 < 32; k0 += 8) {
            unsigned a[2][4];
#pragma unroll
            for (int mt = 0; mt < 2; mt++) {
                int m = wm + mt * 16 + r0;
                a[mt][0] = __float_as_uint(As[m * 36 + k0 + q]);
                a[mt][1] = __float_as_uint(As[(m + 8) * 36 + k0 + q]);
                a[mt][2] = __float_as_uint(As[m * 36 + k0 + q + 4]);
                a[mt][3] = __float_as_uint(As[(m + 8) * 36 + k0 + q + 4]);
            }
#pragma unroll
            for (int nt = 0; nt < 4; nt++) {
                int n = wn + nt * 8 + r0;
                unsigned b0 = __float_as_uint(Bs[n * 36 + k0 + q]);
                unsigned b1 = __float_as_uint(Bs[n * 36 + k0 + q + 4]);
#pragma unroll
                for (int mt = 0; mt < 2; mt++)
                    MMA_TF32(c[mt][nt], a[mt][0], a[mt][1], a[mt][2], a[mt][3], b0, b1);
            }
        }
    };

    const int nb = DM / 32;   // 8
    copy_tile(0, 0);
    copy_tile(32, 1);
#pragma unroll 1
    for (int it = 0; it < nb; it++) {
        cp_wait1();
        __syncthreads();
        compute(it & 1);
        __syncthreads();
        if (it + 2 < nb) copy_tile((it + 2) * 32, it & 1); else cp_commit();
    }

    // exchange fragments via smem (alias pool; mainloop done, barriered)
    float* Cs = pool;   // 128 x 68 = 8704 floats, fits
#pragma unroll
    for (int mt = 0; mt < 2; mt++) {
        int mrow = wm + mt * 16 + r0;
#pragma unroll
        for (int nt = 0; nt < 4; nt++) {
            int ncol = wn + nt * 8 + 2 * q;
#pragma unroll
            for (int i = 0; i < 4; i++) {
                int m = mrow + (i >> 1) * 8;
                int l = ncol + (i & 1);
                Cs[m * 68 + l] = c[mt][nt][i];
            }
        }
    }
    __syncthreads();

    // gates + cell update
#pragma unroll
    for (int ii = 0; ii < 8; ii++) {
        int o = ii * 256 + tid;
        int m = o >> 4, jl = o & 15;
        int grow = bm + m;
        int jg = tb * 16 + jl;
        const float* zr = g_zq + (size_t)grow * G4 + jg;
        float iv = Cs[m * 68 + jl]      + zr[0]    + wsh[jl];
        float fv = Cs[m * 68 + 16 + jl] + zr[512]  + wsh[16 + jl];
        float gv = Cs[m * 68 + 32 + jl] + zr[1024] + wsh[32 + jl];
        float ov = Cs[m * 68 + 48 + jl] + zr[1536] + wsh[48 + jl];
        float cp = g_c[grow * HHs + jg];
        float c2 = sigf(fv) * cp + sigf(iv) * tanhf(gv);
        g_c[grow * HHs + jg] = c2;
        if (jg < DM)
            hout[grow * DM + jg] = g_query_g[grow * DM + jg] + sigf(ov) * tanhf(c2);
    }
}

// ---------------- LayerNorm ----------------
__global__ __launch_bounds__(256) void ln_kernel(const float* __restrict__ ln_g,
                                                 const float* __restrict__ ln_b)
{
    __shared__ float red[256];
    int m = blockIdx.x, t = threadIdx.x;
    float x = g_hpre[m * DM + t];
    float mu = block_reduce(x, red) * (1.f / DM);
    float dx = x - mu;
    float var = block_reduce(dx * dx, red) * (1.f / DM);
    g_query_g[m * DM + t] = dx * rsqrtf(var + 1e-5f) * ln_g[t] + ln_b[t];
}

// ---------------- LSTM step 1 (h_r = 0 -> z = zq) ----------------
__global__ __launch_bounds__(256) void lstm_cell_first(float* __restrict__ hout)
{
    int idx = blockIdx.x * 256 + threadIdx.x;
    int m = idx >> 9, j = idx & 511;
    const float* zr = g_zq + (size_t)m * G4;
    float iv = zr[j], gv = zr[1024 + j], ov = zr[1536 + j];
    float c2 = sigf(iv) * tanhf(gv);   // c_prev = 0
    g_c[idx] = c2;
    if (j < DM) {
        float h2 = sigf(ov) * tanhf(c2);
        hout[m * DM + j] = g_query_g[m * DM + j] + h2;
    }
}

// ---------------- final cosine score ----------------
__global__ __launch_bounds__(256) void final_kernel(const float* __restrict__ h,
                                                    float* __restrict__ out)
{
    int warp = threadIdx.x >> 5, lane = threadIdx.x & 31;
    int m = blockIdx.x * 8 + warp;
    float d = 0.f, hh = 0.f;
#pragma unroll
    for (int jj = 0; jj < 8; jj++) {
        int j = lane + 32 * jj;
        float hv = h[m * DM + j];
        d += hv * g_support_g[j];
        hh += hv * hv;
    }
    d = warp_sum(d); hh = warp_sum(hh);
    if (lane == 0) out[m] = d / (fmaxf(sqrtf(hh), 1e-12f) * g_sg_norm);
}

// ---------------- launch ----------------
extern "C" void kernel_launch(void* const* d_in, const int* in_sizes, int n_in,
                              void* d_out, int out_size)
{
    const float* emb     = (const float*)d_in[0];
    const float* gcn_W   = (const float*)d_in[1];
    const float* gcn_wb  = (const float*)d_in[2];
    const float* gate_W  = (const float*)d_in[3];
    const float* gate_b  = (const float*)d_in[4];
    const float* se_w1   = (const float*)d_in[5];
    const float* se_b1   = (const float*)d_in[6];
    const float* se_w2   = (const float*)d_in[7];
    const float* se_b2   = (const float*)d_in[8];
    const float* ln_g    = (const float*)d_in[9];
    const float* ln_b    = (const float*)d_in[10];
    const float* W_ih    = (const float*)d_in[11];
    const float* W_hh    = (const float*)d_in[12];
    const float* b_ih    = (const float*)d_in[13];
    const float* b_hh    = (const float*)d_in[14];
    const int*   query   = (const int*)d_in[15];
    const int*   support = (const int*)d_in[16];
    const int*   qlc     = (const int*)d_in[17];
    const int*   qrc     = (const int*)d_in[19];
    const int*   slc     = (const int*)d_in[21];
    const int*   src_    = (const int*)d_in[23];
    const int*   knn_tab = (const int*)d_in[25];
    float* out = (float*)d_out;

    float *p_qn, *p_qg, *p_h1, *p_hpre, *p_zq, *p_hA, *p_hB;
    cudaGetSymbolAddress((void**)&p_qn,   g_query_n);
    cudaGetSymbolAddress((void**)&p_qg,   g_query_g);
    cudaGetSymbolAddress((void**)&p_h1,   g_h1);
    cudaGetSymbolAddress((void**)&p_hpre, g_hpre);
    cudaGetSymbolAddress((void**)&p_zq,   g_zq);
    cudaGetSymbolAddress((void**)&p_hA,   g_hA);
    cudaGetSymbolAddress((void**)&p_hB,   g_hB);

    static int attr_done = 0;
    if (!attr_done) {
        cudaFuncSetAttribute(tf32_gemm_cp<64, 1>, cudaFuncAttributeMaxDynamicSharedMemorySize, GEMM64_SMEM);
        cudaFuncSetAttribute(tf32_gemm_cp<64, 2>, cudaFuncAttributeMaxDynamicSharedMemorySize, GEMM64_SMEM);
        cudaFuncSetAttribute(tf32_gemm_cp<128, 3>, cudaFuncAttributeMaxDynamicSharedMemorySize, GEMM128_SMEM);
        cudaFuncSetAttribute(lstm_step_fused, cudaFuncAttributeMaxDynamicSharedMemorySize, GEMM64_SMEM);
        attr_done = 1;
    }

    // launch 0: support-side neighbor encoders (10 blocks)
    neighbor_enc_kernel<<<2 * BS, 256>>>(emb, gcn_W, gcn_wb, gate_W, gate_b,
                                         query, support, qlc, qrc, slc, src_, knn_tab, 2 * BQ);
    // 1-3: support SE + reduce + recurrent term
    support_row_kernel<<<BS, 256>>>(se_w1, se_b1, se_w2, se_b2, ln_g, ln_b);
    support_reduce_kernel<<<1, 256>>>();
    whh_sg_kernel<<<G4 / 8, 256>>>(W_hh);

    // launch 4: query-side neighbor encoders (4096 blocks) — lands in ncu slot
    neighbor_enc_kernel<<<2 * BQ, 256>>>(emb, gcn_W, gcn_wb, gate_W, gate_b,
                                         query, support, qlc, qrc, slc, src_, knn_tab, 0);

    // 5-7: query SE
    {
        dim3 g1(HHs / 64, BQ / 128);
        tf32_gemm_cp<64, 1><<<g1, 256, GEMM64_SMEM>>>(p_qn, DM, se_w1, DM, p_h1, BQ, HHs, DM, se_b1, nullptr, nullptr);
        dim3 g2(DM / 64, BQ / 128);
        tf32_gemm_cp<64, 2><<<g2, 256, GEMM64_SMEM>>>(p_h1, HHs, se_w2, HHs, p_hpre, BQ, DM, HHs, se_b2, nullptr, p_qn);
        ln_kernel<<<BQ, 256>>>(ln_g, ln_b);
    }

    // 8: zq = query_g @ W_ih^T + b_ih + b_hh
    dim3 g3(G4 / 128, BQ / 128);
    tf32_gemm_cp<128, 3><<<g3, 256, GEMM128_SMEM>>>(p_qg, DM, W_ih, DM, p_zq, BQ, G4, DM, b_ih, b_hh, nullptr);

    // 9: step 1 (no GEMM), h -> hA
    lstm_cell_first<<<(BQ * HHs) / 256, 256>>>(p_hA);

    // 10-12: steps 2..4 fused, ping-pong
    dim3 gf(HHs / 16, BQ / 128);   // (32, 16)
    lstm_step_fused<<<gf, 256, GEMM64_SMEM>>>(p_hA, W_hh, p_hB);
    lstm_step_fused<<<gf, 256, GEMM64_SMEM>>>(p_hB, W_hh, p_hA);
    lstm_step_fused<<<gf, 256, GEMM64_SMEM>>>(p_hA, W_hh, p_hB);

    // 13: cosine score
    final_kernel<<<BQ / 8, 256>>>(p_hB, out);
}

// round 8
// speedup vs baseline: 1.5984x; 1.0174x over previous
#include <cuda_runtime.h>
#include <math.h>
#include <stdint.h>

#define VV      200000
#define EE      128
#define PAD_ID  199999
#define KK      32
#define BQ      2048
#define BS      5
#define NN      128
#define KT      64
#define DM      256
#define HHs     512
#define G4      2048

#define GEMM128_SMEM 73728
#define GEMM64_SMEM  55296

// ---------------- scratch ----------------
__device__ float g_query_n[BQ * DM];
__device__ float g_supp_n[BS * DM];
__device__ float g_se_supp[BS * DM];
__device__ float g_query_g[BQ * DM];
__device__ float g_h1[BQ * HHs];
__device__ float g_hpre[BQ * DM];
__device__ float g_support_g[DM];
__device__ float g_sg_norm;
__device__ float g_whh_sg[G4];
__device__ float g_zq[(size_t)BQ * G4];
__device__ float g_hA[BQ * DM];
__device__ float g_hB[BQ * DM];
__device__ float g_c[BQ * HHs];

// ---------------- helpers ----------------
__device__ __forceinline__ float warp_sum(float v) {
#pragma unroll
    for (int o = 16; o; o >>= 1) v += __shfl_down_sync(0xffffffffu, v, o);
    return v;
}
__device__ __forceinline__ float block_reduce(float v, float* red) {
    int t = threadIdx.x;
    red[t] = v;
    __syncthreads();
#pragma unroll
    for (int s = 128; s > 0; s >>= 1) {
        if (t < s) red[t] += red[t + s];
        __syncthreads();
    }
    float r = red[0];
    __syncthreads();
    return r;
}
__device__ __forceinline__ float sigf(float x) { return 1.f / (1.f + expf(-x)); }
__device__ __forceinline__ uint32_t smem_u32(const void* p) {
    return (uint32_t)__cvta_generic_to_shared(p);
}
__device__ __forceinline__ void cp_async16(uint32_t s, const void* g) {
    asm volatile("cp.async.ca.shared.global [%0], [%1], 16;" :: "r"(s), "l"(g));
}
__device__ __forceinline__ void cp_commit() { asm volatile("cp.async.commit_group;"); }
__device__ __forceinline__ void cp_wait1() { asm volatile("cp.async.wait_group 1;"); }

#define MMA_TF32(cc, a0, a1, a2, a3, b0, b1)                                   \
    asm volatile(                                                              \
        "mma.sync.aligned.m16n8k8.row.col.f32.tf32.tf32.f32 "                  \
        "{%0,%1,%2,%3}, {%4,%5,%6,%7}, {%8,%9}, {%0,%1,%2,%3};"                \
        : "+f"((cc)[0]), "+f"((cc)[1]), "+f"((cc)[2]), "+f"((cc)[3])           \
        : "r"(a0), "r"(a1), "r"(a2), "r"(a3), "r"(b0), "r"(b1))

// ---------------- kernel 1: neighbor encoder (one block per row-side) ----------------
__global__ __launch_bounds__(256) void neighbor_enc_kernel(
    const float* __restrict__ emb, const float* __restrict__ gcn_W,
    const float* __restrict__ gcn_wb, const float* __restrict__ gate_W,
    const float* __restrict__ gate_b, const int* __restrict__ query,
    const int* __restrict__ support, const int* __restrict__ qlc,
    const int* __restrict__ qrc, const int* __restrict__ slc,
    const int* __restrict__ src_, const int* __restrict__ knn_tab, int base)
{
    __shared__ float cs[EE];
    __shared__ float pv[EE];
    __shared__ float sims[NN + KT];   // [0:128) structural, [128:192) knn
    __shared__ int   nid[NN + KT];
    __shared__ int   kid[KT];
    __shared__ int   wcnt[8];
    __shared__ int   selA[KK], selR[KK], selK[KK];
    __shared__ float cm[2 * EE];
    __shared__ float km[EE];
    __shared__ float strv[EE], knm[EE];
    __shared__ float red[256];
    __shared__ float s_ncc, s_alpha;

    int b = blockIdx.x + base, t = threadIdx.x;
    int lane = t & 31, warp = t >> 5;

    const int* conn; int eid; float* dst; int row;
    if (b < BQ)                 { row = b;               conn = qlc  + row * NN * 2; eid = query[2 * row];       dst = g_query_n + row * DM; }
    else if (b < 2 * BQ)        { row = b - BQ;          conn = qrc  + row * NN * 2; eid = query[2 * row + 1];   dst = g_query_n + row * DM + EE; }
    else if (b < 2 * BQ + BS)   { row = b - 2 * BQ;      conn = slc  + row * NN * 2; eid = support[2 * row];     dst = g_supp_n  + row * DM; }
    else                        { row = b - 2 * BQ - BS; conn = src_ + row * NN * 2; eid = support[2 * row + 1]; dst = g_supp_n  + row * DM + EE; }
    if (eid < 0 || eid >= VV) eid = PAD_ID;

    if (t < EE) cs[t] = emb[(size_t)eid * EE + t];
    else        pv[t - EE] = emb[(size_t)PAD_ID * EE + (t - EE)];
    if (t < KT) {
        int k = knn_tab[(size_t)eid * KT + t];
        if (k < 0 || k >= VV) k = PAD_ID;
        kid[t] = k;
    }
    __syncthreads();

    float p = (t < EE) ? cs[t] * cs[t] : 0.f;
    float csum = block_reduce(p, red);
    if (t == 0) s_ncc = fmaxf(sqrtf(csum), 1e-8f);
    __syncthreads();
    float ncc = s_ncc;

    const float4* emb4 = (const float4*)emb;
    const float4* cs4  = (const float4*)cs;
    float4 c4 = cs4[lane];

    // ---- combined sims pass: 192 neighbors, 4 gathers in flight per warp ----
#pragma unroll 1
    for (int g = 0; g < 6; g++) {
        int nbase = g * 32 + warp * 4;
        int ids[4]; float4 v[4];
#pragma unroll
        for (int j = 0; j < 4; j++) {
            int n = nbase + j;
            ids[j] = (n < NN) ? conn[2 * n + 1] : kid[n - NN];
            v[j] = emb4[(size_t)ids[j] * 32 + lane];
        }
#pragma unroll
        for (int j = 0; j < 4; j++) {
            float d = v[j].x * c4.x + v[j].y * c4.y + v[j].z * c4.z + v[j].w * c4.w;
            float q = v[j].x * v[j].x + v[j].y * v[j].y + v[j].z * v[j].z + v[j].w * v[j].w;
            d = warp_sum(d); q = warp_sum(q);
            if (lane == 0) {
                int n = nbase + j;
                sims[n] = d / (fmaxf(sqrtf(q), 1e-8f) * ncc);
                nid[n] = ids[j];
            }
        }
    }
    __syncthreads();

    // ---- combined rank counting (matches lax.top_k tie-break), ballot compaction ----
    bool sel = false;
    if (t < NN) {
        float si = sims[t]; int r = 0;
#pragma unroll 8
        for (int j = 0; j < NN; j++) {
            float sj = sims[j];
            r += (sj > si) || (sj == si && j < t);
        }
        sel = (r < KK);
    } else if (t < NN + KT) {
        float si = sims[t]; int r = 0;
#pragma unroll 8
        for (int j = 0; j < KT; j++) {
            float sj = sims[NN + j];
            r += (sj > si) || (sj == si && j < t - NN);
        }
        sel = (r < KK);
    }
    unsigned m = __ballot_sync(0xffffffffu, sel);
    if (lane == 0) wcnt[warp] = __popc(m);
    __syncthreads();
    if (sel) {
        int pos = __popc(m & ((1u << lane) - 1));
        if (t < NN) {
            for (int w = 0; w < warp; w++) pos += wcnt[w];
            selA[pos] = nid[t];
            selR[pos] = conn[2 * t];
        } else {
            for (int w = 4; w < warp; w++) pos += wcnt[w];
            selK[pos] = nid[t];
        }
    }
    __syncthreads();

    // ---- means accumulation (feature-per-thread, deterministic order) ----
    if (t < EE) {
        float acc = 0.f;
#pragma unroll 4
        for (int s = 0; s < KK; s++) acc += emb[(size_t)selA[s] * EE + t];
        cm[EE + t] = acc * (1.f / KK);
        float acc2 = 0.f;
#pragma unroll 4
        for (int s = 0; s < KK; s++) acc2 += emb[(size_t)selK[s] * EE + t];
        km[t] = acc2 * (1.f / KK);
    } else {
        int f = t - EE;
        float acc = 0.f;
#pragma unroll 4
        for (int s = 0; s < KK; s++) acc += emb[(size_t)selR[s] * EE + f];
        cm[f] = acc * (1.f / KK);
    }
    __syncthreads();

    // ---- GCN matvecs (mean commutes with linear map) ----
#pragma unroll 1
    for (int i = 0; i < EE / 8; i++) {
        int e = warp + 8 * i;
        const float* wrow = gcn_W + e * 2 * EE;
        float a1 = 0.f, a2 = 0.f;
#pragma unroll
        for (int jj = 0; jj < 8; jj++) {
            int d = lane + 32 * jj;
            a1 += cm[d] * wrow[d];
        }
#pragma unroll
        for (int jj = 0; jj < 4; jj++) {
            int d = lane + 32 * jj;
            a2 += km[d] * wrow[EE + d] + pv[d] * wrow[d];
        }
        a1 = warp_sum(a1); a2 = warp_sum(a2);
        if (lane == 0) {
            strv[e] = tanhf(a1 + gcn_wb[e]);
            knm[e]  = tanhf(a2 + gcn_wb[e]);
        }
    }
    __syncthreads();

    float gp = (t < EE) ? (strv[t] * gate_W[t] + knm[t] * gate_W[EE + t]) : 0.f;
    float gl = block_reduce(gp, red);
    if (t == 0) s_alpha = sigf(gl + gate_b[0]);
    __syncthreads();
    float a = s_alpha;
    if (t < EE) dst[t] = (1.f - a) * strv[t] + a * knm[t];
}

// ---------------- support encoder ----------------
__global__ __launch_bounds__(256) void support_row_kernel(
    const float* __restrict__ se_w1, const float* __restrict__ se_b1,
    const float* __restrict__ se_w2, const float* __restrict__ se_b2,
    const float* __restrict__ ln_g, const float* __restrict__ ln_b)
{
    __shared__ float xs[DM];
    __shared__ float h1s[HHs];
    __shared__ float red[256];
    int r = blockIdx.x, t = threadIdx.x;

    xs[t] = g_supp_n[r * DM + t];
    __syncthreads();

#pragma unroll
    for (int h = 0; h < 2; h++) {
        int n = t + h * 256;
        const float* wr = se_w1 + (size_t)n * DM;
        float acc = 0.f;
        for (int k = 0; k < DM; k++) acc += xs[k] * wr[k];
        h1s[n] = fmaxf(acc + se_b1[n], 0.f);
    }
    __syncthreads();

    const float* wr = se_w2 + (size_t)t * HHs;
    float acc = 0.f;
    for (int k = 0; k < HHs; k++) acc += h1s[k] * wr[k];
    float x = acc + se_b2[t] + xs[t];

    float mu = block_reduce(x, red) * (1.f / DM);
    float dx = x - mu;
    float var = block_reduce(dx * dx, red) * (1.f / DM);
    g_se_supp[r * DM + t] = dx * rsqrtf(var + 1e-5f) * ln_g[t] + ln_b[t];
}

// ---------------- fused: support mean/norm + whh_sg ----------------
__global__ __launch_bounds__(256) void support_reduce_whh_kernel(const float* __restrict__ W_hh)
{
    __shared__ float sg[DM];
    __shared__ float red[256];
    int t = threadIdx.x;
    float s = 0.f;
#pragma unroll
    for (int r = 0; r < BS; r++) s += g_se_supp[r * DM + t];
    float v = s * (1.f / BS);
    sg[t] = v;
    if (blockIdx.x == 0) {
        g_support_g[t] = v;
        float nrm = block_reduce(v * v, red);
        if (t == 0) g_sg_norm = fmaxf(sqrtf(nrm), 1e-12f);
    }
    __syncthreads();

    int warp = t >> 5, lane = t & 31;
    int n = blockIdx.x * 8 + warp;
    const float* wr = W_hh + (size_t)n * HHs + DM;
    float acc = 0.f;
#pragma unroll
    for (int jj = 0; jj < 8; jj++) {
        int j = lane + 32 * jj;
        acc += wr[j] * sg[j];
    }
    acc = warp_sum(acc);
    if (lane == 0) g_whh_sg[n] = acc;
}

// ================= cp.async tf32 GEMM =================
template<int BN, int MODE>
__global__ __launch_bounds__(256) void tf32_gemm_cp(
    const float* __restrict__ A, int lda, const float* __restrict__ B, int ldb,
    float* __restrict__ C, int M, int N, int K,
    const float* __restrict__ bias, const float* __restrict__ bias2,
    const float* __restrict__ add)
{
    constexpr int NT = BN / 16;
    constexpr int ASTG = 128 * 36;
    constexpr int BSTG = BN * 36;
    extern __shared__ float pool[];
    float* Ab = pool;
    float* Bb = pool + 2 * ASTG;

    int tid = threadIdx.x, lane = tid & 31, wid = tid >> 5;
    int bm = blockIdx.y * 128, bn = blockIdx.x * BN;
    int wm = (wid >> 1) * 32, wn = (wid & 1) * (BN / 2);
    int r0 = lane >> 2, q = lane & 3;

    float c[2][NT][4];
#pragma unroll
    for (int mt = 0; mt < 2; mt++)
#pragma unroll
        for (int nt = 0; nt < NT; nt++)
#pragma unroll
            for (int i = 0; i < 4; i++) c[mt][nt][i] = 0.f;

    auto copy_tile = [&](int kt, int stage) {
        float* As = Ab + stage * ASTG;
        float* Bs = Bb + stage * BSTG;
#pragma unroll
        for (int i = 0; i < 4; i++) {
            int ci = i * 256 + tid;
            int row = ci >> 3, c4 = (ci & 7) * 4;
            cp_async16(smem_u32(As + row * 36 + c4),
                       A + (size_t)(bm + row) * lda + kt + c4);
        }
#pragma unroll
        for (int i = 0; i < BN / 32; i++) {
            int ci = i * 256 + tid;
            int row = ci >> 3, c4 = (ci & 7) * 4;
            cp_async16(smem_u32(Bs + row * 36 + c4),
                       B + (size_t)(bn + row) * ldb + kt + c4);
        }
        cp_commit();
    };

    auto compute = [&](int stage) {
        const float* As = Ab + stage * ASTG;
        const float* Bs = Bb + stage * BSTG;
#pragma unroll
        for (int k0 = 0; k0 < 32; k0 += 8) {
            unsigned a[2][4];
#pragma unroll
            for (int mt = 0; mt < 2; mt++) {
                int m = wm + mt * 16 + r0;
                a[mt][0] = __float_as_uint(As[m * 36 + k0 + q]);
                a[mt][1] = __float_as_uint(As[(m + 8) * 36 + k0 + q]);
                a[mt][2] = __float_as_uint(As[m * 36 + k0 + q + 4]);
                a[mt][3] = __float_as_uint(As[(m + 8) * 36 + k0 + q + 4]);
            }
#pragma unroll
            for (int nt = 0; nt < NT; nt++) {
                int n = wn + nt * 8 + r0;
                unsigned b0 = __float_as_uint(Bs[n * 36 + k0 + q]);
                unsigned b1 = __float_as_uint(Bs[n * 36 + k0 + q + 4]);
#pragma unroll
                for (int mt = 0; mt < 2; mt++)
                    MMA_TF32(c[mt][nt], a[mt][0], a[mt][1], a[mt][2], a[mt][3], b0, b1);
            }
        }
    };

    int nb = K / 32;
    copy_tile(0, 0);
    if (nb > 1) copy_tile(32, 1); else cp_commit();

#pragma unroll 1
    for (int it = 0; it < nb; it++) {
        cp_wait1();
        __syncthreads();
        compute(it & 1);
        __syncthreads();
        if (it + 2 < nb) copy_tile((it + 2) * 32, it & 1); else cp_commit();
    }

#pragma unroll
    for (int mt = 0; mt < 2; mt++) {
        int mrow = bm + wm + mt * 16 + r0;
#pragma unroll
        for (int nt = 0; nt < NT; nt++) {
            int ncol = bn + wn + nt * 8 + 2 * q;
#pragma unroll
            for (int i = 0; i < 4; i++) {
                int m = mrow + (i >> 1) * 8;
                int n = ncol + (i & 1);
                float v = c[mt][nt][i];
                if (MODE == 1)      v = fmaxf(v + bias[n], 0.f);
                else if (MODE == 2) v = v + bias[n] + add[(size_t)m * N + n];
                else if (MODE == 3) v = v + bias[n] + bias2[n];
                C[(size_t)m * N + n] = v;
            }
        }
    }
}

// ---------------- fused LSTM step ----------------
__global__ __launch_bounds__(256) void lstm_step_fused(
    const float* __restrict__ hin, const float* __restrict__ W_hh,
    float* __restrict__ hout)
{
    constexpr int ASTG = 128 * 36;
    constexpr int BSTG = 64 * 36;
    extern __shared__ float pool[];
    __shared__ float wsh[64];
    float* Ab = pool;
    float* Bb = pool + 2 * ASTG;

    int tid = threadIdx.x, lane = tid & 31, wid = tid >> 5;
    int tb = blockIdx.x;
    int bm = blockIdx.y * 128;
    int wm = (wid >> 1) * 32, wn = (wid & 1) * 32;
    int r0 = lane >> 2, q = lane & 3;

    float c[2][4][4];
#pragma unroll
    for (int mt = 0; mt < 2; mt++)
#pragma unroll
        for (int nt = 0; nt < 4; nt++)
#pragma unroll
            for (int i = 0; i < 4; i++) c[mt][nt][i] = 0.f;

    if (tid < 64) wsh[tid] = g_whh_sg[(tid >> 4) * 512 + tb * 16 + (tid & 15)];

    auto copy_tile = [&](int kt, int stage) {
        float* As = Ab + stage * ASTG;
        float* Bs = Bb + stage * BSTG;
#pragma unroll
        for (int i = 0; i < 4; i++) {
            int ci = i * 256 + tid;
            int row = ci >> 3, c4 = (ci & 7) * 4;
            cp_async16(smem_u32(As + row * 36 + c4),
                       hin + (size_t)(bm + row) * DM + kt + c4);
        }
#pragma unroll
        for (int i = 0; i < 2; i++) {
            int ci = i * 256 + tid;
            int row = ci >> 3, c4 = (ci & 7) * 4;
            int grow = (row >> 4) * 512 + tb * 16 + (row & 15);
            cp_async16(smem_u32(Bs + row * 36 + c4),
                       W_hh + (size_t)grow * HHs + kt + c4);
        }
        cp_commit();
    };

    auto compute = [&](int stage) {
        const float* As = Ab + stage * ASTG;
        const float* Bs = Bb + stage * BSTG;
#pragma unroll
        for (int k0 = 0; k0 < 32; k0 += 8) {
            unsigned a[2][4];
#pragma unroll
            for (int mt = 0; mt < 2; mt++) {
                int m = wm + mt * 16 + r0;
                a[mt][0] = __float_as_uint(As[m * 36 + k0 + q]);
                a[mt][1] = __float_as_uint(As[(m + 8) * 36 + k0 + q]);
                a[mt][2] = __float_as_uint(As[m * 36 + k0 + q + 4]);
                a[mt][3] = __float_as_uint(As[(m + 8) * 36 + k0 + q + 4]);
            }
#pragma unroll
            for (int nt = 0; nt < 4; nt++) {
                int n = wn + nt * 8 + r0;
                unsigned b0 = __float_as_uint(Bs[n * 36 + k0 + q]);
                unsigned b1 = __float_as_uint(Bs[n * 36 + k0 + q + 4]);
#pragma unroll
                for (int mt = 0; mt < 2; mt++)
                    MMA_TF32(c[mt][nt], a[mt][0], a[mt][1], a[mt][2], a[mt][3], b0, b1);
            }
        }
    };

    const int nb = DM / 32;   // 8
    copy_tile(0, 0);
    copy_tile(32, 1);
#pragma unroll 1
    for (int it = 0; it < nb; it++) {
        cp_wait1();
        __syncthreads();
        compute(it & 1);
        __syncthreads();
        if (it + 2 < nb) copy_tile((it + 2) * 32, it & 1); else cp_commit();
    }

    float* Cs = pool;   // 128 x 68
#pragma unroll
    for (int mt = 0; mt < 2; mt++) {
        int mrow = wm + mt * 16 + r0;
#pragma unroll
        for (int nt = 0; nt < 4; nt++) {
            int ncol = wn + nt * 8 + 2 * q;
#pragma unroll
            for (int i = 0; i < 4; i++) {
                int m = mrow + (i >> 1) * 8;
                int l = ncol + (i & 1);
                Cs[m * 68 + l] = c[mt][nt][i];
            }
        }
    }
    __syncthreads();

#pragma unroll
    for (int ii = 0; ii < 8; ii++) {
        int o = ii * 256 + tid;
        int m = o >> 4, jl = o & 15;
        int grow = bm + m;
        int jg = tb * 16 + jl;
        const float* zr = g_zq + (size_t)grow * G4 + jg;
        float iv = Cs[m * 68 + jl]      + zr[0]    + wsh[jl];
        float fv = Cs[m * 68 + 16 + jl] + zr[512]  + wsh[16 + jl];
        float gv = Cs[m * 68 + 32 + jl] + zr[1024] + wsh[32 + jl];
        float ov = Cs[m * 68 + 48 + jl] + zr[1536] + wsh[48 + jl];
        float cp = g_c[grow * HHs + jg];
        float c2 = sigf(fv) * cp + sigf(iv) * tanhf(gv);
        g_c[grow * HHs + jg] = c2;
        if (jg < DM)
            hout[grow * DM + jg] = g_query_g[grow * DM + jg] + sigf(ov) * tanhf(c2);
    }
}

// ---------------- LayerNorm ----------------
__global__ __launch_bounds__(256) void ln_kernel(const float* __restrict__ ln_g,
                                                 const float* __restrict__ ln_b)
{
    __shared__ float red[256];
    int m = blockIdx.x, t = threadIdx.x;
    float x = g_hpre[m * DM + t];
    float mu = block_reduce(x, red) * (1.f / DM);
    float dx = x - mu;
    float var = block_reduce(dx * dx, red) * (1.f / DM);
    g_query_g[m * DM + t] = dx * rsqrtf(var + 1e-5f) * ln_g[t] + ln_b[t];
}

// ---------------- LSTM step 1 ----------------
__global__ __launch_bounds__(256) void lstm_cell_first(float* __restrict__ hout)
{
    int idx = blockIdx.x * 256 + threadIdx.x;
    int m = idx >> 9, j = idx & 511;
    const float* zr = g_zq + (size_t)m * G4;
    float iv = zr[j], gv = zr[1024 + j], ov = zr[1536 + j];
    float c2 = sigf(iv) * tanhf(gv);   // c_prev = 0
    g_c[idx] = c2;
    if (j < DM) {
        float h2 = sigf(ov) * tanhf(c2);
        hout[m * DM + j] = g_query_g[m * DM + j] + h2;
    }
}

// ---------------- final cosine score ----------------
__global__ __launch_bounds__(256) void final_kernel(const float* __restrict__ h,
                                                    float* __restrict__ out)
{
    int warp = threadIdx.x >> 5, lane = threadIdx.x & 31;
    int m = blockIdx.x * 8 + warp;
    float d = 0.f, hh = 0.f;
#pragma unroll
    for (int jj = 0; jj < 8; jj++) {
        int j = lane + 32 * jj;
        float hv = h[m * DM + j];
        d += hv * g_support_g[j];
        hh += hv * hv;
    }
    d = warp_sum(d); hh = warp_sum(hh);
    if (lane == 0) out[m] = d / (fmaxf(sqrtf(hh), 1e-12f) * g_sg_norm);
}

// ---------------- launch ----------------
extern "C" void kernel_launch(void* const* d_in, const int* in_sizes, int n_in,
                              void* d_out, int out_size)
{
    const float* emb     = (const float*)d_in[0];
    const float* gcn_W   = (const float*)d_in[1];
    const float* gcn_wb  = (const float*)d_in[2];
    const float* gate_W  = (const float*)d_in[3];
    const float* gate_b  = (const float*)d_in[4];
    const float* se_w1   = (const float*)d_in[5];
    const float* se_b1   = (const float*)d_in[6];
    const float* se_w2   = (const float*)d_in[7];
    const float* se_b2   = (const float*)d_in[8];
    const float* ln_g    = (const float*)d_in[9];
    const float* ln_b    = (const float*)d_in[10];
    const float* W_ih    = (const float*)d_in[11];
    const float* W_hh    = (const float*)d_in[12];
    const float* b_ih    = (const float*)d_in[13];
    const float* b_hh    = (const float*)d_in[14];
    const int*   query   = (const int*)d_in[15];
    const int*   support = (const int*)d_in[16];
    const int*   qlc     = (const int*)d_in[17];
    const int*   qrc     = (const int*)d_in[19];
    const int*   slc     = (const int*)d_in[21];
    const int*   src_    = (const int*)d_in[23];
    const int*   knn_tab = (const int*)d_in[25];
    float* out = (float*)d_out;

    float *p_qn, *p_qg, *p_h1, *p_hpre, *p_zq, *p_hA, *p_hB;
    cudaGetSymbolAddress((void**)&p_qn,   g_query_n);
    cudaGetSymbolAddress((void**)&p_qg,   g_query_g);
    cudaGetSymbolAddress((void**)&p_h1,   g_h1);
    cudaGetSymbolAddress((void**)&p_hpre, g_hpre);
    cudaGetSymbolAddress((void**)&p_zq,   g_zq);
    cudaGetSymbolAddress((void**)&p_hA,   g_hA);
    cudaGetSymbolAddress((void**)&p_hB,   g_hB);

    static int attr_done = 0;
    if (!attr_done) {
        cudaFuncSetAttribute(tf32_gemm_cp<64, 1>, cudaFuncAttributeMaxDynamicSharedMemorySize, GEMM64_SMEM);
        cudaFuncSetAttribute(tf32_gemm_cp<64, 2>, cudaFuncAttributeMaxDynamicSharedMemorySize, GEMM64_SMEM);
        cudaFuncSetAttribute(tf32_gemm_cp<128, 3>, cudaFuncAttributeMaxDynamicSharedMemorySize, GEMM128_SMEM);
        cudaFuncSetAttribute(lstm_step_fused, cudaFuncAttributeMaxDynamicSharedMemorySize, GEMM64_SMEM);
        attr_done = 1;
    }

    // 0: support-side neighbor encoders (10 blocks)
    neighbor_enc_kernel<<<2 * BS, 256>>>(emb, gcn_W, gcn_wb, gate_W, gate_b,
                                         query, support, qlc, qrc, slc, src_, knn_tab, 2 * BQ);
    // 1: support SE
    support_row_kernel<<<BS, 256>>>(se_w1, se_b1, se_w2, se_b2, ln_g, ln_b);
    // 2: fused support reduce + whh_sg
    support_reduce_whh_kernel<<<G4 / 8, 256>>>(W_hh);

    // 3: query-side neighbor encoders (4096 blocks) — profiled slot
    neighbor_enc_kernel<<<2 * BQ, 256>>>(emb, gcn_W, gcn_wb, gate_W, gate_b,
                                         query, support, qlc, qrc, slc, src_, knn_tab, 0);

    // 4-6: query SE
    {
        dim3 g1(HHs / 64, BQ / 128);
        tf32_gemm_cp<64, 1><<<g1, 256, GEMM64_SMEM>>>(p_qn, DM, se_w1, DM, p_h1, BQ, HHs, DM, se_b1, nullptr, nullptr);
        dim3 g2(DM / 64, BQ / 128);
        tf32_gemm_cp<64, 2><<<g2, 256, GEMM64_SMEM>>>(p_h1, HHs, se_w2, HHs, p_hpre, BQ, DM, HHs, se_b2, nullptr, p_qn);
        ln_kernel<<<BQ, 256>>>(ln_g, ln_b);
    }

    // 7: zq
    dim3 g3(G4 / 128, BQ / 128);
    tf32_gemm_cp<128, 3><<<g3, 256, GEMM128_SMEM>>>(p_qg, DM, W_ih, DM, p_zq, BQ, G4, DM, b_ih, b_hh, nullptr);

    // 8: step 1
    lstm_cell_first<<<(BQ * HHs) / 256, 256>>>(p_hA);

    // 9-11: steps 2..4 fused
    dim3 gf(HHs / 16, BQ / 128);
    lstm_step_fused<<<gf, 256, GEMM64_SMEM>>>(p_hA, W_hh, p_hB);
    lstm_step_fused<<<gf, 256, GEMM64_SMEM>>>(p_hB, W_hh, p_hA);
    lstm_step_fused<<<gf, 256, GEMM64_SMEM>>>(p_hA, W_hh, p_hB);

    // 12: cosine score
    final_kernel<<<BQ / 8, 256>>>(p_hB, out);
}

// round 14
// speedup vs baseline: 1.6195x; 1.0132x over previous
#include <cuda_runtime.h>
#include <math.h>
#include <stdint.h>

#define VV      200000
#define EE      128
#define PAD_ID  199999
#define KK      32
#define BQ      2048
#define BS      5
#define NN      128
#define KT      64
#define DM      256
#define HHs     512
#define G4      2048

#define GEMM128_SMEM 73728
#define GEMM64_SMEM  55296

// ---------------- scratch ----------------
__device__ float g_query_n[BQ * DM];
__device__ float g_supp_n[BS * DM];
__device__ float g_se_supp[BS * DM];
__device__ float g_query_g[BQ * DM];
__device__ float g_h1[BQ * HHs];
__device__ float g_hpre[BQ * DM];
__device__ float g_support_g[DM];
__device__ float g_sg_norm;
__device__ float g_whh_sg[G4];
__device__ float g_zq[(size_t)BQ * G4];
__device__ float g_hA[BQ * DM];
__device__ float g_hB[BQ * DM];
__device__ float g_c[BQ * HHs];

// ---------------- helpers ----------------
__device__ __forceinline__ float warp_sum(float v) {
#pragma unroll
    for (int o = 16; o; o >>= 1) v += __shfl_down_sync(0xffffffffu, v, o);
    return v;
}
// reduce two values across a warp simultaneously:
// after this, sd holds the d-sum (valid where needed via lane 0 path), sq = q-sum broadcast.
__device__ __forceinline__ void warp_sum2(float d, float q, float& sd, float& sq) {
    float od = __shfl_xor_sync(0xffffffffu, d, 16);
    float oq = __shfl_xor_sync(0xffffffffu, q, 16);
    int lane = threadIdx.x & 31;
    float v = (lane < 16) ? (d + od) : (q + oq);
#pragma unroll
    for (int o = 8; o; o >>= 1) v += __shfl_xor_sync(0xffffffffu, v, o);
    sd = v;                                   // valid on lanes 0-15 (d-sum)
    sq = __shfl_sync(0xffffffffu, v, 16);     // q-sum broadcast
}
__device__ __forceinline__ float block_reduce(float v, float* red) {
    int t = threadIdx.x;
    red[t] = v;
    __syncthreads();
#pragma unroll
    for (int s = 128; s > 0; s >>= 1) {
        if (t < s) red[t] += red[t + s];
        __syncthreads();
    }
    float r = red[0];
    __syncthreads();
    return r;
}
__device__ __forceinline__ float sigf(float x) { return 1.f / (1.f + expf(-x)); }
__device__ __forceinline__ uint32_t smem_u32(const void* p) {
    return (uint32_t)__cvta_generic_to_shared(p);
}
__device__ __forceinline__ void cp_async16(uint32_t s, const void* g) {
    asm volatile("cp.async.ca.shared.global [%0], [%1], 16;" :: "r"(s), "l"(g));
}
__device__ __forceinline__ void cp_commit() { asm volatile("cp.async.commit_group;"); }
__device__ __forceinline__ void cp_wait1() { asm volatile("cp.async.wait_group 1;"); }

// order-preserving float->uint map (canonicalizes -0 to +0):
// u(a) < u(b)  <=>  a < b ; u(a) == u(b) <=> a == b (after -0 canonicalization)
__device__ __forceinline__ uint32_t f2ord(float f) {
    uint32_t b = __float_as_uint(f);
    if (b == 0x80000000u) b = 0u;             // -0 -> +0
    return (b & 0x80000000u) ? ~b : (b | 0x80000000u);
}

#define MMA_TF32(cc, a0, a1, a2, a3, b0, b1)                                   \
    asm volatile(                                                              \
        "mma.sync.aligned.m16n8k8.row.col.f32.tf32.tf32.f32 "                  \
        "{%0,%1,%2,%3}, {%4,%5,%6,%7}, {%8,%9}, {%0,%1,%2,%3};"                \
        : "+f"((cc)[0]), "+f"((cc)[1]), "+f"((cc)[2]), "+f"((cc)[3])           \
        : "r"(a0), "r"(a1), "r"(a2), "r"(a3), "r"(b0), "r"(b1))

// ---------------- kernel 1: neighbor encoder (one block per row-side) ----------------
__global__ __launch_bounds__(256, 6) void neighbor_enc_kernel(
    const float* __restrict__ emb, const float* __restrict__ gcn_W,
    const float* __restrict__ gcn_wb, const float* __restrict__ gate_W,
    const float* __restrict__ gate_b, const int* __restrict__ query,
    const int* __restrict__ support, const int* __restrict__ qlc,
    const int* __restrict__ qrc, const int* __restrict__ slc,
    const int* __restrict__ src_, const int* __restrict__ knn_tab, int base)
{
    __shared__ float cs[EE];
    __shared__ float pv[EE];
    __shared__ uint32_t usims[NN + KT];   // ordered-uint sims: [0:128) structural, [128:192) knn
    __shared__ int   nid[NN + KT];
    __shared__ int   kid[KT];
    __shared__ int   wcnt[8];
    __shared__ int   selA[KK], selR[KK], selK[KK];
    __shared__ float cm[2 * EE];
    __shared__ float km[EE];
    __shared__ float strv[EE], knm[EE];
    __shared__ float red[256];
    __shared__ float s_ncc, s_alpha;

    int b = blockIdx.x + base, t = threadIdx.x;
    int lane = t & 31, warp = t >> 5;

    const int* conn; int eid; float* dst; int row;
    if (b < BQ)                 { row = b;               conn = qlc  + row * NN * 2; eid = query[2 * row];       dst = g_query_n + row * DM; }
    else if (b < 2 * BQ)        { row = b - BQ;          conn = qrc  + row * NN * 2; eid = query[2 * row + 1];   dst = g_query_n + row * DM + EE; }
    else if (b < 2 * BQ + BS)   { row = b - 2 * BQ;      conn = slc  + row * NN * 2; eid = support[2 * row];     dst = g_supp_n  + row * DM; }
    else                        { row = b - 2 * BQ - BS; conn = src_ + row * NN * 2; eid = support[2 * row + 1]; dst = g_supp_n  + row * DM + EE; }
    if (eid < 0 || eid >= VV) eid = PAD_ID;

    if (t < EE) cs[t] = emb[(size_t)eid * EE + t];
    else        pv[t - EE] = emb[(size_t)PAD_ID * EE + (t - EE)];
    if (t < KT) {
        int k = knn_tab[(size_t)eid * KT + t];
        if (k < 0 || k >= VV) k = PAD_ID;
        kid[t] = k;
    }
    __syncthreads();

    float p = (t < EE) ? cs[t] * cs[t] : 0.f;
    float csum = block_reduce(p, red);
    if (t == 0) s_ncc = fmaxf(sqrtf(csum), 1e-8f);
    __syncthreads();
    float ncc = s_ncc;

    const float4* emb4 = (const float4*)emb;
    const float4* cs4  = (const float4*)cs;
    float4 c4 = cs4[lane];

    // ---- combined sims pass: 192 neighbors, 4 gathers in flight per warp ----
#pragma unroll 1
    for (int g = 0; g < 6; g++) {
        int nbase = g * 32 + warp * 4;
        int ids[4]; float4 v[4];
#pragma unroll
        for (int j = 0; j < 4; j++) {
            int n = nbase + j;
            ids[j] = (n < NN) ? conn[2 * n + 1] : kid[n - NN];
            v[j] = emb4[(size_t)ids[j] * 32 + lane];
        }
#pragma unroll
        for (int j = 0; j < 4; j++) {
            float d = v[j].x * c4.x + v[j].y * c4.y + v[j].z * c4.z + v[j].w * c4.w;
            float q = v[j].x * v[j].x + v[j].y * v[j].y + v[j].z * v[j].z + v[j].w * v[j].w;
            float sd, sq;
            warp_sum2(d, q, sd, sq);
            if (lane == 0) {
                int n = nbase + j;
                float sim = sd / (fmaxf(sqrtf(sq), 1e-8f) * ncc);
                usims[n] = f2ord(sim);
                nid[n] = ids[j];
            }
        }
    }
    __syncthreads();

    // ---- rank counting via split loops on ordered uints (== lax.top_k tie-break) ----
    // rank_i = #{j<i: u_j >= u_i} + #{j>i: u_j > u_i}
    bool sel = false;
    if (t < NN) {
        uint32_t ui = usims[t];
        int r = 0;
#pragma unroll 4
        for (int j = 0; j < t; j++) r += (usims[j] >= ui);
#pragma unroll 4
        for (int j = t + 1; j < NN; j++) r += (usims[j] > ui);
        sel = (r < KK);
    } else if (t < NN + KT) {
        uint32_t ui = usims[t];
        int r = 0;
#pragma unroll 4
        for (int j = NN; j < t; j++) r += (usims[j] >= ui);
#pragma unroll 4
        for (int j = t + 1; j < NN + KT; j++) r += (usims[j] > ui);
        sel = (r < KK);
    }
    unsigned m = __ballot_sync(0xffffffffu, sel);
    if (lane == 0) wcnt[warp] = __popc(m);
    __syncthreads();
    if (sel) {
        int pos = __popc(m & ((1u << lane) - 1));
        if (t < NN) {
            for (int w = 0; w < warp; w++) pos += wcnt[w];
            selA[pos] = nid[t];
            selR[pos] = conn[2 * t];
        } else {
            for (int w = 4; w < warp; w++) pos += wcnt[w];
            selK[pos] = nid[t];
        }
    }
    __syncthreads();

    // ---- means accumulation (feature-per-thread, deterministic order) ----
    if (t < EE) {
        float acc = 0.f;
#pragma unroll 4
        for (int s = 0; s < KK; s++) acc += emb[(size_t)selA[s] * EE + t];
        cm[EE + t] = acc * (1.f / KK);
        float acc2 = 0.f;
#pragma unroll 4
        for (int s = 0; s < KK; s++) acc2 += emb[(size_t)selK[s] * EE + t];
        km[t] = acc2 * (1.f / KK);
    } else {
        int f = t - EE;
        float acc = 0.f;
#pragma unroll 4
        for (int s = 0; s < KK; s++) acc += emb[(size_t)selR[s] * EE + f];
        cm[f] = acc * (1.f / KK);
    }
    __syncthreads();

    // ---- GCN matvecs (mean commutes with linear map) ----
#pragma unroll 1
    for (int i = 0; i < EE / 8; i++) {
        int e = warp + 8 * i;
        const float* wrow = gcn_W + e * 2 * EE;
        float a1 = 0.f, a2 = 0.f;
#pragma unroll
        for (int jj = 0; jj < 8; jj++) {
            int d = lane + 32 * jj;
            a1 += cm[d] * wrow[d];
        }
#pragma unroll
        for (int jj = 0; jj < 4; jj++) {
            int d = lane + 32 * jj;
            a2 += km[d] * wrow[EE + d] + pv[d] * wrow[d];
        }
        float s1, s2;
        warp_sum2(a1, a2, s1, s2);
        if (lane == 0) {
            strv[e] = tanhf(s1 + gcn_wb[e]);
            knm[e]  = tanhf(s2 + gcn_wb[e]);
        }
    }
    __syncthreads();

    float gp = (t < EE) ? (strv[t] * gate_W[t] + knm[t] * gate_W[EE + t]) : 0.f;
    float gl = block_reduce(gp, red);
    if (t == 0) s_alpha = sigf(gl + gate_b[0]);
    __syncthreads();
    float a = s_alpha;
    if (t < EE) dst[t] = (1.f - a) * strv[t] + a * knm[t];
}

// ---------------- support encoder ----------------
__global__ __launch_bounds__(256) void support_row_kernel(
    const float* __restrict__ se_w1, const float* __restrict__ se_b1,
    const float* __restrict__ se_w2, const float* __restrict__ se_b2,
    const float* __restrict__ ln_g, const float* __restrict__ ln_b)
{
    __shared__ float xs[DM];
    __shared__ float h1s[HHs];
    __shared__ float red[256];
    int r = blockIdx.x, t = threadIdx.x;

    xs[t] = g_supp_n[r * DM + t];
    __syncthreads();

#pragma unroll
    for (int h = 0; h < 2; h++) {
        int n = t + h * 256;
        const float* wr = se_w1 + (size_t)n * DM;
        float acc = 0.f;
        for (int k = 0; k < DM; k++) acc += xs[k] * wr[k];
        h1s[n] = fmaxf(acc + se_b1[n], 0.f);
    }
    __syncthreads();

    const float* wr = se_w2 + (size_t)t * HHs;
    float acc = 0.f;
    for (int k = 0; k < HHs; k++) acc += h1s[k] * wr[k];
    float x = acc + se_b2[t] + xs[t];

    float mu = block_reduce(x, red) * (1.f / DM);
    float dx = x - mu;
    float var = block_reduce(dx * dx, red) * (1.f / DM);
    g_se_supp[r * DM + t] = dx * rsqrtf(var + 1e-5f) * ln_g[t] + ln_b[t];
}

// ---------------- fused: support mean/norm + whh_sg ----------------
__global__ __launch_bounds__(256) void support_reduce_whh_kernel(const float* __restrict__ W_hh)
{
    __shared__ float sg[DM];
    __shared__ float red[256];
    int t = threadIdx.x;
    float s = 0.f;
#pragma unroll
    for (int r = 0; r < BS; r++) s += g_se_supp[r * DM + t];
    float v = s * (1.f / BS);
    sg[t] = v;
    if (blockIdx.x == 0) {
        g_support_g[t] = v;
        float nrm = block_reduce(v * v, red);
        if (t == 0) g_sg_norm = fmaxf(sqrtf(nrm), 1e-12f);
    }
    __syncthreads();

    int warp = t >> 5, lane = t & 31;
    int n = blockIdx.x * 8 + warp;
    const float* wr = W_hh + (size_t)n * HHs + DM;
    float acc = 0.f;
#pragma unroll
    for (int jj = 0; jj < 8; jj++) {
        int j = lane + 32 * jj;
        acc += wr[j] * sg[j];
    }
    acc = warp_sum(acc);
    if (lane == 0) g_whh_sg[n] = acc;
}

// ================= cp.async tf32 GEMM =================
template<int BN, int MODE>
__global__ __launch_bounds__(256) void tf32_gemm_cp(
    const float* __restrict__ A, int lda, const float* __restrict__ B, int ldb,
    float* __restrict__ C, int M, int N, int K,
    const float* __restrict__ bias, const float* __restrict__ bias2,
    const float* __restrict__ add)
{
    constexpr int NT = BN / 16;
    constexpr int ASTG = 128 * 36;
    constexpr int BSTG = BN * 36;
    extern __shared__ float pool[];
    float* Ab = pool;
    float* Bb = pool + 2 * ASTG;

    int tid = threadIdx.x, lane = tid & 31, wid = tid >> 5;
    int bm = blockIdx.y * 128, bn = blockIdx.x * BN;
    int wm = (wid >> 1) * 32, wn = (wid & 1) * (BN / 2);
    int r0 = lane >> 2, q = lane & 3;

    float c[2][NT][4];
#pragma unroll
    for (int mt = 0; mt < 2; mt++)
#pragma unroll
        for (int nt = 0; nt < NT; nt++)
#pragma unroll
            for (int i = 0; i < 4; i++) c[mt][nt][i] = 0.f;

    auto copy_tile = [&](int kt, int stage) {
        float* As = Ab + stage * ASTG;
        float* Bs = Bb + stage * BSTG;
#pragma unroll
        for (int i = 0; i < 4; i++) {
            int ci = i * 256 + tid;
            int row = ci >> 3, c4 = (ci & 7) * 4;
            cp_async16(smem_u32(As + row * 36 + c4),
                       A + (size_t)(bm + row) * lda + kt + c4);
        }
#pragma unroll
        for (int i = 0; i < BN / 32; i++) {
            int ci = i * 256 + tid;
            int row = ci >> 3, c4 = (ci & 7) * 4;
            cp_async16(smem_u32(Bs + row * 36 + c4),
                       B + (size_t)(bn + row) * ldb + kt + c4);
        }
        cp_commit();
    };

    auto compute = [&](int stage) {
        const float* As = Ab + stage * ASTG;
        const float* Bs = Bb + stage * BSTG;
#pragma unroll
        for (int k0 = 0; k0 < 32; k0 += 8) {
            unsigned a[2][4];
#pragma unroll
            for (int mt = 0; mt < 2; mt++) {
                int m = wm + mt * 16 + r0;
                a[mt][0] = __float_as_uint(As[m * 36 + k0 + q]);
                a[mt][1] = __float_as_uint(As[(m + 8) * 36 + k0 + q]);
                a[mt][2] = __float_as_uint(As[m * 36 + k0 + q + 4]);
                a[mt][3] = __float_as_uint(As[(m + 8) * 36 + k0 + q + 4]);
            }
#pragma unroll
            for (int nt = 0; nt < NT; nt++) {
                int n = wn + nt * 8 + r0;
                unsigned b0 = __float_as_uint(Bs[n * 36 + k0 + q]);
                unsigned b1 = __float_as_uint(Bs[n * 36 + k0 + q + 4]);
#pragma unroll
                for (int mt = 0; mt < 2; mt++)
                    MMA_TF32(c[mt][nt], a[mt][0], a[mt][1], a[mt][2], a[mt][3], b0, b1);
            }
        }
    };

    int nb = K / 32;
    copy_tile(0, 0);
    if (nb > 1) copy_tile(32, 1); else cp_commit();

#pragma unroll 1
    for (int it = 0; it < nb; it++) {
        cp_wait1();
        __syncthreads();
        compute(it & 1);
        __syncthreads();
        if (it + 2 < nb) copy_tile((it + 2) * 32, it & 1); else cp_commit();
    }

#pragma unroll
    for (int mt = 0; mt < 2; mt++) {
        int mrow = bm + wm + mt * 16 + r0;
#pragma unroll
        for (int nt = 0; nt < NT; nt++) {
            int ncol = bn + wn + nt * 8 + 2 * q;
#pragma unroll
            for (int i = 0; i < 4; i++) {
                int m = mrow + (i >> 1) * 8;
                int n = ncol + (i & 1);
                float v = c[mt][nt][i];
                if (MODE == 1)      v = fmaxf(v + bias[n], 0.f);
                else if (MODE == 2) v = v + bias[n] + add[(size_t)m * N + n];
                else if (MODE == 3) v = v + bias[n] + bias2[n];
                C[(size_t)m * N + n] = v;
            }
        }
    }
}

// ---------------- fused LSTM step ----------------
__global__ __launch_bounds__(256) void lstm_step_fused(
    const float* __restrict__ hin, const float* __restrict__ W_hh,
    float* __restrict__ hout)
{
    constexpr int ASTG = 128 * 36;
    constexpr int BSTG = 64 * 36;
    extern __shared__ float pool[];
    __shared__ float wsh[64];
    float* Ab = pool;
    float* Bb = pool + 2 * ASTG;

    int tid = threadIdx.x, lane = tid & 31, wid = tid >> 5;
    int tb = blockIdx.x;
    int bm = blockIdx.y * 128;
    int wm = (wid >> 1) * 32, wn = (wid & 1) * 32;
    int r0 = lane >> 2, q = lane & 3;

    float c[2][4][4];
#pragma unroll
    for (int mt = 0; mt < 2; mt++)
#pragma unroll
        for (int nt = 0; nt < 4; nt++)
#pragma unroll
            for (int i = 0; i < 4; i++) c[mt][nt][i] = 0.f;

    if (tid < 64) wsh[tid] = g_whh_sg[(tid >> 4) * 512 + tb * 16 + (tid & 15)];

    auto copy_tile = [&](int kt, int stage) {
        float* As = Ab + stage * ASTG;
        float* Bs = Bb + stage * BSTG;
#pragma unroll
        for (int i = 0; i < 4; i++) {
            int ci = i * 256 + tid;
            int row = ci >> 3, c4 = (ci & 7) * 4;
            cp_async16(smem_u32(As + row * 36 + c4),
                       hin + (size_t)(bm + row) * DM + kt + c4);
        }
#pragma unroll
        for (int i = 0; i < 2; i++) {
            int ci = i * 256 + tid;
            int row = ci >> 3, c4 = (ci & 7) * 4;
            int grow = (row >> 4) * 512 + tb * 16 + (row & 15);
            cp_async16(smem_u32(Bs + row * 36 + c4),
                       W_hh + (size_t)grow * HHs + kt + c4);
        }
        cp_commit();
    };

    auto compute = [&](int stage) {
        const float* As = Ab + stage * ASTG;
        const float* Bs = Bb + stage * BSTG;
#pragma unroll
        for (int k0 = 0; k0 < 32; k0 += 8) {
            unsigned a[2][4];
#pragma unroll
            for (int mt = 0; mt < 2; mt++) {
                int m = wm + mt * 16 + r0;
                a[mt][0] = __float_as_uint(As[m * 36 + k0 + q]);
                a[mt][1] = __float_as_uint(As[(m + 8) * 36 + k0 + q]);
                a[mt][2] = __float_as_uint(As[m * 36 + k0 + q + 4]);
                a[mt][3] = __float_as_uint(As[(m + 8) * 36 + k0 + q + 4]);
            }
#pragma unroll
            for (int nt = 0; nt < 4; nt++) {
                int n = wn + nt * 8 + r0;
                unsigned b0 = __float_as_uint(Bs[n * 36 + k0 + q]);
                unsigned b1 = __float_as_uint(Bs[n * 36 + k0 + q + 4]);
#pragma unroll
                for (int mt = 0; mt < 2; mt++)
                    MMA_TF32(c[mt][nt], a[mt][0], a[mt][1], a[mt][2], a[mt][3], b0, b1);
            }
        }
    };

    const int nb = DM / 32;   // 8
    copy_tile(0, 0);
    copy_tile(32, 1);
#pragma unroll 1
    for (int it = 0; it < nb; it++) {
        cp_wait1();
        __syncthreads();
        compute(it & 1);
        __syncthreads();
        if (it + 2 < nb) copy_tile((it + 2) * 32, it & 1); else cp_commit();
    }

    float* Cs = pool;   // 128 x 68
#pragma unroll
    for (int mt = 0; mt < 2; mt++) {
        int mrow = wm + mt * 16 + r0;
#pragma unroll
        for (int nt = 0; nt < 4; nt++) {
            int ncol = wn + nt * 8 + 2 * q;
#pragma unroll
            for (int i = 0; i < 4; i++) {
                int m = mrow + (i >> 1) * 8;
                int l = ncol + (i & 1);
                Cs[m * 68 + l] = c[mt][nt][i];
            }
        }
    }
    __syncthreads();

#pragma unroll
    for (int ii = 0; ii < 8; ii++) {
        int o = ii * 256 + tid;
        int m = o >> 4, jl = o & 15;
        int grow = bm + m;
        int jg = tb * 16 + jl;
        const float* zr = g_zq + (size_t)grow * G4 + jg;
        float iv = Cs[m * 68 + jl]      + zr[0]    + wsh[jl];
        float fv = Cs[m * 68 + 16 + jl] + zr[512]  + wsh[16 + jl];
        float gv = Cs[m * 68 + 32 + jl] + zr[1024] + wsh[32 + jl];
        float ov = Cs[m * 68 + 48 + jl] + zr[1536] + wsh[48 + jl];
        float cp = g_c[grow * HHs + jg];
        float c2 = sigf(fv) * cp + sigf(iv) * tanhf(gv);
        g_c[grow * HHs + jg] = c2;
        if (jg < DM)
            hout[grow * DM + jg] = g_query_g[grow * DM + jg] + sigf(ov) * tanhf(c2);
    }
}

// ---------------- LayerNorm ----------------
__global__ __launch_bounds__(256) void ln_kernel(const float* __restrict__ ln_g,
                                                 const float* __restrict__ ln_b)
{
    __shared__ float red[256];
    int m = blockIdx.x, t = threadIdx.x;
    float x = g_hpre[m * DM + t];
    float mu = block_reduce(x, red) * (1.f / DM);
    float dx = x - mu;
    float var = block_reduce(dx * dx, red) * (1.f / DM);
    g_query_g[m * DM + t] = dx * rsqrtf(var + 1e-5f) * ln_g[t] + ln_b[t];
}

// ---------------- LSTM step 1 ----------------
__global__ __launch_bounds__(256) void lstm_cell_first(float* __restrict__ hout)
{
    int idx = blockIdx.x * 256 + threadIdx.x;
    int m = idx >> 9, j = idx & 511;
    const float* zr = g_zq + (size_t)m * G4;
    float iv = zr[j], gv = zr[1024 + j], ov = zr[1536 + j];
    float c2 = sigf(iv) * tanhf(gv);   // c_prev = 0
    g_c[idx] = c2;
    if (j < DM) {
        float h2 = sigf(ov) * tanhf(c2);
        hout[m * DM + j] = g_query_g[m * DM + j] + h2;
    }
}

// ---------------- final cosine score ----------------
__global__ __launch_bounds__(256) void final_kernel(const float* __restrict__ h,
                                                    float* __restrict__ out)
{
    int warp = threadIdx.x >> 5, lane = threadIdx.x & 31;
    int m = blockIdx.x * 8 + warp;
    float d = 0.f, hh = 0.f;
#pragma unroll
    for (int jj = 0; jj < 8; jj++) {
        int j = lane + 32 * jj;
        float hv = h[m * DM + j];
        d += hv * g_support_g[j];
        hh += hv * hv;
    }
    d = warp_sum(d); hh = warp_sum(hh);
    if (lane == 0) out[m] = d / (fmaxf(sqrtf(hh), 1e-12f) * g_sg_norm);
}

// ---------------- launch ----------------
extern "C" void kernel_launch(void* const* d_in, const int* in_sizes, int n_in,
                              void* d_out, int out_size)
{
    const float* emb     = (const float*)d_in[0];
    const float* gcn_W   = (const float*)d_in[1];
    const float* gcn_wb  = (const float*)d_in[2];
    const float* gate_W  = (const float*)d_in[3];
    const float* gate_b  = (const float*)d_in[4];
    const float* se_w1   = (const float*)d_in[5];
    const float* se_b1   = (const float*)d_in[6];
    const float* se_w2   = (const float*)d_in[7];
    const float* se_b2   = (const float*)d_in[8];
    const float* ln_g    = (const float*)d_in[9];
    const float* ln_b    = (const float*)d_in[10];
    const float* W_ih    = (const float*)d_in[11];
    const float* W_hh    = (const float*)d_in[12];
    const float* b_ih    = (const float*)d_in[13];
    const float* b_hh    = (const float*)d_in[14];
    const int*   query   = (const int*)d_in[15];
    const int*   support = (const int*)d_in[16];
    const int*   qlc     = (const int*)d_in[17];
    const int*   qrc     = (const int*)d_in[19];
    const int*   slc     = (const int*)d_in[21];
    const int*   src_    = (const int*)d_in[23];
    const int*   knn_tab = (const int*)d_in[25];
    float* out = (float*)d_out;

    float *p_qn, *p_qg, *p_h1, *p_hpre, *p_zq, *p_hA, *p_hB;
    cudaGetSymbolAddress((void**)&p_qn,   g_query_n);
    cudaGetSymbolAddress((void**)&p_qg,   g_query_g);
    cudaGetSymbolAddress((void**)&p_h1,   g_h1);
    cudaGetSymbolAddress((void**)&p_hpre, g_hpre);
    cudaGetSymbolAddress((void**)&p_zq,   g_zq);
    cudaGetSymbolAddress((void**)&p_hA,   g_hA);
    cudaGetSymbolAddress((void**)&p_hB,   g_hB);

    static int attr_done = 0;
    if (!attr_done) {
        cudaFuncSetAttribute(tf32_gemm_cp<64, 1>, cudaFuncAttributeMaxDynamicSharedMemorySize, GEMM64_SMEM);
        cudaFuncSetAttribute(tf32_gemm_cp<64, 2>, cudaFuncAttributeMaxDynamicSharedMemorySize, GEMM64_SMEM);
        cudaFuncSetAttribute(tf32_gemm_cp<128, 3>, cudaFuncAttributeMaxDynamicSharedMemorySize, GEMM128_SMEM);
        cudaFuncSetAttribute(lstm_step_fused, cudaFuncAttributeMaxDynamicSharedMemorySize, GEMM64_SMEM);
        attr_done = 1;
    }

    // 0: support-side neighbor encoders (10 blocks)
    neighbor_enc_kernel<<<2 * BS, 256>>>(emb, gcn_W, gcn_wb, gate_W, gate_b,
                                         query, support, qlc, qrc, slc, src_, knn_tab, 2 * BQ);
    // 1: support SE
    support_row_kernel<<<BS, 256>>>(se_w1, se_b1, se_w2, se_b2, ln_g, ln_b);
    // 2: fused support reduce + whh_sg
    support_reduce_whh_kernel<<<G4 / 8, 256>>>(W_hh);

    // 3: query-side neighbor encoders (4096 blocks) — profiled slot
    neighbor_enc_kernel<<<2 * BQ, 256>>>(emb, gcn_W, gcn_wb, gate_W, gate_b,
                                         query, support, qlc, qrc, slc, src_, knn_tab, 0);

    // 4-6: query SE
    {
        dim3 g1(HHs / 64, BQ / 128);
        tf32_gemm_cp<64, 1><<<g1, 256, GEMM64_SMEM>>>(p_qn, DM, se_w1, DM, p_h1, BQ, HHs, DM, se_b1, nullptr, nullptr);
        dim3 g2(DM / 64, BQ / 128);
        tf32_gemm_cp<64, 2><<<g2, 256, GEMM64_SMEM>>>(p_h1, HHs, se_w2, HHs, p_hpre, BQ, DM, HHs, se_b2, nullptr, p_qn);
        ln_kernel<<<BQ, 256>>>(ln_g, ln_b);
    }

    // 7: zq
    dim3 g3(G4 / 128, BQ / 128);
    tf32_gemm_cp<128, 3><<<g3, 256, GEMM128_SMEM>>>(p_qg, DM, W_ih, DM, p_zq, BQ, G4, DM, b_ih, b_hh, nullptr);

    // 8: step 1
    lstm_cell_first<<<(BQ * HHs) / 256, 256>>>(p_hA);

    // 9-11: steps 2..4 fused
    dim3 gf(HHs / 16, BQ / 128);
    lstm_step_fused<<<gf, 256, GEMM64_SMEM>>>(p_hA, W_hh, p_hB);
    lstm_step_fused<<<gf, 256, GEMM64_SMEM>>>(p_hB, W_hh, p_hA);
    lstm_step_fused<<<gf, 256, GEMM64_SMEM>>>(p_hA, W_hh, p_hB);

    // 12: cosine score
    final_kernel<<<BQ / 8, 256>>>(p_hB, out);
}

// round 16
// speedup vs baseline: 1.7747x; 1.0958x over previous
#include <cuda_runtime.h>
#include <math.h>
#include <stdint.h>

#define VV      200000
#define EE      128
#define PAD_ID  199999
#define KK      32
#define BQ      2048
#define BS      5
#define NN      128
#define KT      64
#define DM      256
#define HHs     512
#define G4      2048
#define NR      (2 * BQ + 2 * BS)   // 4106 row-sides
#define NRP     4224                // padded to 33*128

#define GEMM128_SMEM 73728
#define GEMM64_SMEM  55296

// ---------------- scratch ----------------
__device__ float g_query_n[BQ * DM];
__device__ float g_supp_n[BS * DM];
__device__ float g_se_supp[BS * DM];
__device__ float g_query_g[BQ * DM];
__device__ float g_h1[BQ * HHs];
__device__ float g_hpre[BQ * DM];
__device__ float g_support_g[DM];
__device__ float g_sg_norm;
__device__ float g_whh_sg[G4];
__device__ float g_zq[(size_t)BQ * G4];
__device__ float g_hA[BQ * DM];
__device__ float g_hB[BQ * DM];
__device__ float g_c[BQ * HHs];
__device__ float g_cm[(size_t)NRP * 256];
__device__ float g_km[(size_t)NRP * EE];
__device__ float g_strv[(size_t)NRP * EE];
__device__ float g_knm[(size_t)NRP * EE];
__device__ float g_pvw[EE];

// ---------------- helpers ----------------
__device__ __forceinline__ float warp_sum(float v) {
#pragma unroll
    for (int o = 16; o; o >>= 1) v += __shfl_down_sync(0xffffffffu, v, o);
    return v;
}
__device__ __forceinline__ void warp_sum2(float d, float q, float& sd, float& sq) {
    float od = __shfl_xor_sync(0xffffffffu, d, 16);
    float oq = __shfl_xor_sync(0xffffffffu, q, 16);
    int lane = threadIdx.x & 31;
    float v = (lane < 16) ? (d + od) : (q + oq);
#pragma unroll
    for (int o = 8; o; o >>= 1) v += __shfl_xor_sync(0xffffffffu, v, o);
    sd = v;
    sq = __shfl_sync(0xffffffffu, v, 16);
}
__device__ __forceinline__ float block_reduce(float v, float* red) {
    int t = threadIdx.x;
    red[t] = v;
    __syncthreads();
#pragma unroll
    for (int s = 128; s > 0; s >>= 1) {
        if (t < s) red[t] += red[t + s];
        __syncthreads();
    }
    float r = red[0];
    __syncthreads();
    return r;
}
__device__ __forceinline__ float sigf(float x) { return 1.f / (1.f + expf(-x)); }
__device__ __forceinline__ uint32_t smem_u32(const void* p) {
    return (uint32_t)__cvta_generic_to_shared(p);
}
__device__ __forceinline__ void cp_async16(uint32_t s, const void* g) {
    asm volatile("cp.async.ca.shared.global [%0], [%1], 16;" :: "r"(s), "l"(g));
}
__device__ __forceinline__ void cp_commit() { asm volatile("cp.async.commit_group;"); }
__device__ __forceinline__ void cp_wait1() { asm volatile("cp.async.wait_group 1;"); }

// order-preserving float->uint (canonicalize -0)
__device__ __forceinline__ uint32_t f2ord(float f) {
    uint32_t b = __float_as_uint(f);
    if (b == 0x80000000u) b = 0u;
    return (b & 0x80000000u) ? ~b : (b | 0x80000000u);
}

#define MMA_TF32(cc, a0, a1, a2, a3, b0, b1)                                   \
    asm volatile(                                                              \
        "mma.sync.aligned.m16n8k8.row.col.f32.tf32.tf32.f32 "                  \
        "{%0,%1,%2,%3}, {%4,%5,%6,%7}, {%8,%9}, {%0,%1,%2,%3};"                \
        : "+f"((cc)[0]), "+f"((cc)[1]), "+f"((cc)[2]), "+f"((cc)[3])           \
        : "r"(a0), "r"(a1), "r"(a2), "r"(a3), "r"(b0), "r"(b1))

// ---------------- kernel 1: neighbor select + means (GCN offloaded) ----------------
__global__ __launch_bounds__(256, 6) void neighbor_sel_kernel(
    const float* __restrict__ emb, const int* __restrict__ query,
    const int* __restrict__ support, const int* __restrict__ qlc,
    const int* __restrict__ qrc, const int* __restrict__ slc,
    const int* __restrict__ src_, const int* __restrict__ knn_tab, int base)
{
    __shared__ float cs[EE];
    __shared__ unsigned long long ukey[NN + KT];
    __shared__ int   nid[NN + KT];
    __shared__ int   kid[KT];
    __shared__ int   wcnt[8];
    __shared__ int   selA[KK], selR[KK], selK[KK];
    __shared__ float red[256];
    __shared__ float s_ncc;

    int b = blockIdx.x + base, t = threadIdx.x;
    int lane = t & 31, warp = t >> 5;

    const int* conn; int eid;
    if (b < BQ)               { conn = qlc  + b * NN * 2;            eid = query[2 * b]; }
    else if (b < 2 * BQ)      { int r = b - BQ; conn = qrc + r * NN * 2; eid = query[2 * r + 1]; }
    else if (b < 2 * BQ + BS) { int r = b - 2 * BQ; conn = slc + r * NN * 2; eid = support[2 * r]; }
    else                      { int r = b - 2 * BQ - BS; conn = src_ + r * NN * 2; eid = support[2 * r + 1]; }
    if (eid < 0 || eid >= VV) eid = PAD_ID;

    if (t < EE) cs[t] = emb[(size_t)eid * EE + t];
    if (t < KT) {
        int k = knn_tab[(size_t)eid * KT + t];
        if (k < 0 || k >= VV) k = PAD_ID;
        kid[t] = k;
    }
    __syncthreads();

    float p = (t < EE) ? cs[t] * cs[t] : 0.f;
    float csum = block_reduce(p, red);
    if (t == 0) s_ncc = fmaxf(sqrtf(csum), 1e-8f);
    __syncthreads();
    float ncc = s_ncc;

    const float4* emb4 = (const float4*)emb;
    const float4* cs4  = (const float4*)cs;
    float4 c4 = cs4[lane];

    // ---- combined sims: 192 neighbors, 4 gathers in flight per warp ----
#pragma unroll 1
    for (int g = 0; g < 6; g++) {
        int nbase = g * 32 + warp * 4;
        int ids[4]; float4 v[4];
#pragma unroll
        for (int j = 0; j < 4; j++) {
            int n = nbase + j;
            ids[j] = (n < NN) ? conn[2 * n + 1] : kid[n - NN];
            v[j] = emb4[(size_t)ids[j] * 32 + lane];
        }
#pragma unroll
        for (int j = 0; j < 4; j++) {
            float d = v[j].x * c4.x + v[j].y * c4.y + v[j].z * c4.z + v[j].w * c4.w;
            float q = v[j].x * v[j].x + v[j].y * v[j].y + v[j].z * v[j].z + v[j].w * v[j].w;
            float sd, sq;
            warp_sum2(d, q, sd, sq);
            if (lane == 0) {
                int n = nbase + j;
                float sim = sd / (fmaxf(sqrtf(sq), 1e-8f) * ncc);
                ukey[n] = ((unsigned long long)f2ord(sim) << 32) | (unsigned)(255 - n);
                nid[n] = ids[j];
            }
        }
    }
    __syncthreads();

    // ---- rank via 64-bit keys: rank_i = #{j: key_j > key_i}; fixed bounds, unrollable ----
    // key encodes (sim desc, index asc) => exactly lax.top_k ordering
    bool sel = false;
    if (t < NN) {
        unsigned long long ki = ukey[t]; int r = 0;
#pragma unroll 8
        for (int j = 0; j < NN; j++) r += (ukey[j] > ki);
        sel = (r < KK);
    } else if (t < NN + KT) {
        unsigned long long ki = ukey[t]; int r = 0;
#pragma unroll 8
        for (int j = NN; j < NN + KT; j++) r += (ukey[j] > ki);
        sel = (r < KK);
    }
    unsigned m = __ballot_sync(0xffffffffu, sel);
    if (lane == 0) wcnt[warp] = __popc(m);
    __syncthreads();
    if (sel) {
        int pos = __popc(m & ((1u << lane) - 1));
        if (t < NN) {
            for (int w = 0; w < warp; w++) pos += wcnt[w];
            selA[pos] = nid[t];
            selR[pos] = conn[2 * t];
        } else {
            for (int w = 4; w < warp; w++) pos += wcnt[w];
            selK[pos] = nid[t];
        }
    }
    __syncthreads();

    // ---- means -> GLOBAL (GCN matvec done later by batched GEMM) ----
    if (t < EE) {
        float acc = 0.f, acc2 = 0.f;
#pragma unroll 4
        for (int s = 0; s < KK; s++) {
            acc  += emb[(size_t)selA[s] * EE + t];
            acc2 += emb[(size_t)selK[s] * EE + t];
        }
        g_cm[(size_t)b * 256 + EE + t] = acc * (1.f / KK);   // ent mean
        g_km[(size_t)b * EE + t]       = acc2 * (1.f / KK);  // knn mean
    } else {
        int f = t - EE;
        float acc = 0.f;
#pragma unroll 4
        for (int s = 0; s < KK; s++) acc += emb[(size_t)selR[s] * EE + f];
        g_cm[(size_t)b * 256 + f] = acc * (1.f / KK);        // rel mean
    }
}

// ---------------- pvW[e] = sum_d emb[PAD,d] * gcn_W[e,d] ----------------
__global__ __launch_bounds__(256) void pvw_kernel(const float* __restrict__ emb,
                                                  const float* __restrict__ gcn_W)
{
    __shared__ float pv[EE];
    int t = threadIdx.x, lane = t & 31, warp = t >> 5;
    if (t < EE) pv[t] = emb[(size_t)PAD_ID * EE + t];
    __syncthreads();
#pragma unroll 1
    for (int i = 0; i < EE / 8; i++) {
        int e = warp + 8 * i;
        const float* wr = gcn_W + (size_t)e * 2 * EE;
        float a = 0.f;
#pragma unroll
        for (int jj = 0; jj < 4; jj++) {
            int d = lane + 32 * jj;
            a += pv[d] * wr[d];
        }
        a = warp_sum(a);
        if (lane == 0) g_pvw[e] = a;
    }
}

// ---------------- gate + blend -> query_n / supp_n ----------------
__global__ __launch_bounds__(256) void gate_blend_kernel(const float* __restrict__ gate_W,
                                                         const float* __restrict__ gate_b)
{
    int rs = blockIdx.x * 8 + (threadIdx.x >> 5);
    if (rs >= NR) return;
    int lane = threadIdx.x & 31;
    float sv[4], kv[4], gp = 0.f;
#pragma unroll
    for (int jj = 0; jj < 4; jj++) {
        int d = lane + 32 * jj;
        float s = g_strv[(size_t)rs * EE + d];
        float k = g_knm[(size_t)rs * EE + d];
        sv[jj] = s; kv[jj] = k;
        gp += s * gate_W[d] + k * gate_W[EE + d];
    }
#pragma unroll
    for (int o = 16; o; o >>= 1) gp += __shfl_xor_sync(0xffffffffu, gp, o);
    float a = sigf(gp + gate_b[0]);
    float* dst;
    if (rs < BQ)               dst = g_query_n + (size_t)rs * DM;
    else if (rs < 2 * BQ)      dst = g_query_n + (size_t)(rs - BQ) * DM + EE;
    else if (rs < 2 * BQ + BS) dst = g_supp_n + (size_t)(rs - 2 * BQ) * DM;
    else                       dst = g_supp_n + (size_t)(rs - 2 * BQ - BS) * DM + EE;
#pragma unroll
    for (int jj = 0; jj < 4; jj++) {
        int d = lane + 32 * jj;
        dst[d] = (1.f - a) * sv[jj] + a * kv[jj];
    }
}

// ---------------- support encoder ----------------
__global__ __launch_bounds__(256) void support_row_kernel(
    const float* __restrict__ se_w1, const float* __restrict__ se_b1,
    const float* __restrict__ se_w2, const float* __restrict__ se_b2,
    const float* __restrict__ ln_g, const float* __restrict__ ln_b)
{
    __shared__ float xs[DM];
    __shared__ float h1s[HHs];
    __shared__ float red[256];
    int r = blockIdx.x, t = threadIdx.x;

    xs[t] = g_supp_n[r * DM + t];
    __syncthreads();

#pragma unroll
    for (int h = 0; h < 2; h++) {
        int n = t + h * 256;
        const float* wr = se_w1 + (size_t)n * DM;
        float acc = 0.f;
        for (int k = 0; k < DM; k++) acc += xs[k] * wr[k];
        h1s[n] = fmaxf(acc + se_b1[n], 0.f);
    }
    __syncthreads();

    const float* wr = se_w2 + (size_t)t * HHs;
    float acc = 0.f;
    for (int k = 0; k < HHs; k++) acc += h1s[k] * wr[k];
    float x = acc + se_b2[t] + xs[t];

    float mu = block_reduce(x, red) * (1.f / DM);
    float dx = x - mu;
    float var = block_reduce(dx * dx, red) * (1.f / DM);
    g_se_supp[r * DM + t] = dx * rsqrtf(var + 1e-5f) * ln_g[t] + ln_b[t];
}

// ---------------- fused: support mean/norm + whh_sg ----------------
__global__ __launch_bounds__(256) void support_reduce_whh_kernel(const float* __restrict__ W_hh)
{
    __shared__ float sg[DM];
    __shared__ float red[256];
    int t = threadIdx.x;
    float s = 0.f;
#pragma unroll
    for (int r = 0; r < BS; r++) s += g_se_supp[r * DM + t];
    float v = s * (1.f / BS);
    sg[t] = v;
    if (blockIdx.x == 0) {
        g_support_g[t] = v;
        float nrm = block_reduce(v * v, red);
        if (t == 0) g_sg_norm = fmaxf(sqrtf(nrm), 1e-12f);
    }
    __syncthreads();

    int warp = t >> 5, lane = t & 31;
    int n = blockIdx.x * 8 + warp;
    const float* wr = W_hh + (size_t)n * HHs + DM;
    float acc = 0.f;
#pragma unroll
    for (int jj = 0; jj < 8; jj++) {
        int j = lane + 32 * jj;
        acc += wr[j] * sg[j];
    }
    acc = warp_sum(acc);
    if (lane == 0) g_whh_sg[n] = acc;
}

// ================= cp.async tf32 GEMM =================
// modes: 1 relu(+bias) | 2 +bias+add | 3 +bias+bias2 | 4 tanh(+bias) | 5 tanh(+bias+bias2)
template<int BN, int MODE>
__global__ __launch_bounds__(256) void tf32_gemm_cp(
    const float* __restrict__ A, int lda, const float* __restrict__ B, int ldb,
    float* __restrict__ C, int M, int N, int K,
    const float* __restrict__ bias, const float* __restrict__ bias2,
    const float* __restrict__ add)
{
    constexpr int NT = BN / 16;
    constexpr int ASTG = 128 * 36;
    constexpr int BSTG = BN * 36;
    extern __shared__ float pool[];
    float* Ab = pool;
    float* Bb = pool + 2 * ASTG;

    int tid = threadIdx.x, lane = tid & 31, wid = tid >> 5;
    int bm = blockIdx.y * 128, bn = blockIdx.x * BN;
    int wm = (wid >> 1) * 32, wn = (wid & 1) * (BN / 2);
    int r0 = lane >> 2, q = lane & 3;

    float c[2][NT][4];
#pragma unroll
    for (int mt = 0; mt < 2; mt++)
#pragma unroll
        for (int nt = 0; nt < NT; nt++)
#pragma unroll
            for (int i = 0; i < 4; i++) c[mt][nt][i] = 0.f;

    auto copy_tile = [&](int kt, int stage) {
        float* As = Ab + stage * ASTG;
        float* Bs = Bb + stage * BSTG;
#pragma unroll
        for (int i = 0; i < 4; i++) {
            int ci = i * 256 + tid;
            int row = ci >> 3, c4 = (ci & 7) * 4;
            cp_async16(smem_u32(As + row * 36 + c4),
                       A + (size_t)(bm + row) * lda + kt + c4);
        }
#pragma unroll
        for (int i = 0; i < BN / 32; i++) {
            int ci = i * 256 + tid;
            int row = ci >> 3, c4 = (ci & 7) * 4;
            cp_async16(smem_u32(Bs + row * 36 + c4),
                       B + (size_t)(bn + row) * ldb + kt + c4);
        }
        cp_commit();
    };

    auto compute = [&](int stage) {
        const float* As = Ab + stage * ASTG;
        const float* Bs = Bb + stage * BSTG;
#pragma unroll
        for (int k0 = 0; k0 < 32; k0 += 8) {
            unsigned a[2][4];
#pragma unroll
            for (int mt = 0; mt < 2; mt++) {
                int m = wm + mt * 16 + r0;
                a[mt][0] = __float_as_uint(As[m * 36 + k0 + q]);
                a[mt][1] = __float_as_uint(As[(m + 8) * 36 + k0 + q]);
                a[mt][2] = __float_as_uint(As[m * 36 + k0 + q + 4]);
                a[mt][3] = __float_as_uint(As[(m + 8) * 36 + k0 + q + 4]);
            }
#pragma unroll
            for (int nt = 0; nt < NT; nt++) {
                int n = wn + nt * 8 + r0;
                unsigned b0 = __float_as_uint(Bs[n * 36 + k0 + q]);
                unsigned b1 = __float_as_uint(Bs[n * 36 + k0 + q + 4]);
#pragma unroll
                for (int mt = 0; mt < 2; mt++)
                    MMA_TF32(c[mt][nt], a[mt][0], a[mt][1], a[mt][2], a[mt][3], b0, b1);
            }
        }
    };

    int nb = K / 32;
    copy_tile(0, 0);
    if (nb > 1) copy_tile(32, 1); else cp_commit();

#pragma unroll 1
    for (int it = 0; it < nb; it++) {
        cp_wait1();
        __syncthreads();
        compute(it & 1);
        __syncthreads();
        if (it + 2 < nb) copy_tile((it + 2) * 32, it & 1); else cp_commit();
    }

#pragma unroll
    for (int mt = 0; mt < 2; mt++) {
        int mrow = bm + wm + mt * 16 + r0;
#pragma unroll
        for (int nt = 0; nt < NT; nt++) {
            int ncol = bn + wn + nt * 8 + 2 * q;
#pragma unroll
            for (int i = 0; i < 4; i++) {
                int m = mrow + (i >> 1) * 8;
                int n = ncol + (i & 1);
                float v = c[mt][nt][i];
                if (MODE == 1)      v = fmaxf(v + bias[n], 0.f);
                else if (MODE == 2) v = v + bias[n] + add[(size_t)m * N + n];
                else if (MODE == 3) v = v + bias[n] + bias2[n];
                else if (MODE == 4) v = tanhf(v + bias[n]);
                else if (MODE == 5) v = tanhf(v + bias[n] + bias2[n]);
                C[(size_t)m * N + n] = v;
            }
        }
    }
}

// ---------------- fused LSTM step ----------------
__global__ __launch_bounds__(256) void lstm_step_fused(
    const float* __restrict__ hin, const float* __restrict__ W_hh,
    float* __restrict__ hout)
{
    constexpr int ASTG = 128 * 36;
    constexpr int BSTG = 64 * 36;
    extern __shared__ float pool[];
    __shared__ float wsh[64];
    float* Ab = pool;
    float* Bb = pool + 2 * ASTG;

    int tid = threadIdx.x, lane = tid & 31, wid = tid >> 5;
    int tb = blockIdx.x;
    int bm = blockIdx.y * 128;
    int wm = (wid >> 1) * 32, wn = (wid & 1) * 32;
    int r0 = lane >> 2, q = lane & 3;

    float c[2][4][4];
#pragma unroll
    for (int mt = 0; mt < 2; mt++)
#pragma unroll
        for (int nt = 0; nt < 4; nt++)
#pragma unroll
            for (int i = 0; i < 4; i++) c[mt][nt][i] = 0.f;

    if (tid < 64) wsh[tid] = g_whh_sg[(tid >> 4) * 512 + tb * 16 + (tid & 15)];

    auto copy_tile = [&](int kt, int stage) {
        float* As = Ab + stage * ASTG;
        float* Bs = Bb + stage * BSTG;
#pragma unroll
        for (int i = 0; i < 4; i++) {
            int ci = i * 256 + tid;
            int row = ci >> 3, c4 = (ci & 7) * 4;
            cp_async16(smem_u32(As + row * 36 + c4),
                       hin + (size_t)(bm + row) * DM + kt + c4);
        }
#pragma unroll
        for (int i = 0; i < 2; i++) {
            int ci = i * 256 + tid;
            int row = ci >> 3, c4 = (ci & 7) * 4;
            int grow = (row >> 4) * 512 + tb * 16 + (row & 15);
            cp_async16(smem_u32(Bs + row * 36 + c4),
                       W_hh + (size_t)grow * HHs + kt + c4);
        }
        cp_commit();
    };

    auto compute = [&](int stage) {
        const float* As = Ab + stage * ASTG;
        const float* Bs = Bb + stage * BSTG;
#pragma unroll
        for (int k0 = 0; k0 < 32; k0 += 8) {
            unsigned a[2][4];
#pragma unroll
            for (int mt = 0; mt < 2; mt++) {
                int m = wm + mt * 16 + r0;
                a[mt][0] = __float_as_uint(As[m * 36 + k0 + q]);
                a[mt][1] = __float_as_uint(As[(m + 8) * 36 + k0 + q]);
                a[mt][2] = __float_as_uint(As[m * 36 + k0 + q + 4]);
                a[mt][3] = __float_as_uint(As[(m + 8) * 36 + k0 + q + 4]);
            }
#pragma unroll
            for (int nt = 0; nt < 4; nt++) {
                int n = wn + nt * 8 + r0;
                unsigned b0 = __float_as_uint(Bs[n * 36 + k0 + q]);
                unsigned b1 = __float_as_uint(Bs[n * 36 + k0 + q + 4]);
#pragma unroll
                for (int mt = 0; mt < 2; mt++)
                    MMA_TF32(c[mt][nt], a[mt][0], a[mt][1], a[mt][2], a[mt][3], b0, b1);
            }
        }
    };

    const int nb = DM / 32;   // 8
    copy_tile(0, 0);
    copy_tile(32, 1);
#pragma unroll 1
    for (int it = 0; it < nb; it++) {
        cp_wait1();
        __syncthreads();
        compute(it & 1);
        __syncthreads();
        if (it + 2 < nb) copy_tile((it + 2) * 32, it & 1); else cp_commit();
    }

    float* Cs = pool;   // 128 x 68
#pragma unroll
    for (int mt = 0; mt < 2; mt++) {
        int mrow = wm + mt * 16 + r0;
#pragma unroll
        for (int nt = 0; nt < 4; nt++) {
            int ncol = wn + nt * 8 + 2 * q;
#pragma unroll
            for (int i = 0; i < 4; i++) {
                int m = mrow + (i >> 1) * 8;
                int l = ncol + (i & 1);
                Cs[m * 68 + l] = c[mt][nt][i];
            }
        }
    }
    __syncthreads();

#pragma unroll
    for (int ii = 0; ii < 8; ii++) {
        int o = ii * 256 + tid;
        int m = o >> 4, jl = o & 15;
        int grow = bm + m;
        int jg = tb * 16 + jl;
        const float* zr = g_zq + (size_t)grow * G4 + jg;
        float iv = Cs[m * 68 + jl]      + zr[0]    + wsh[jl];
        float fv = Cs[m * 68 + 16 + jl] + zr[512]  + wsh[16 + jl];
        float gv = Cs[m * 68 + 32 + jl] + zr[1024] + wsh[32 + jl];
        float ov = Cs[m * 68 + 48 + jl] + zr[1536] + wsh[48 + jl];
        float cp = g_c[grow * HHs + jg];
        float c2 = sigf(fv) * cp + sigf(iv) * tanhf(gv);
        g_c[grow * HHs + jg] = c2;
        if (jg < DM)
            hout[grow * DM + jg] = g_query_g[grow * DM + jg] + sigf(ov) * tanhf(c2);
    }
}

// ---------------- LayerNorm ----------------
__global__ __launch_bounds__(256) void ln_kernel(const float* __restrict__ ln_g,
                                                 const float* __restrict__ ln_b)
{
    __shared__ float red[256];
    int m = blockIdx.x, t = threadIdx.x;
    float x = g_hpre[m * DM + t];
    float mu = block_reduce(x, red) * (1.f / DM);
    float dx = x - mu;
    float var = block_reduce(dx * dx, red) * (1.f / DM);
    g_query_g[m * DM + t] = dx * rsqrtf(var + 1e-5f) * ln_g[t] + ln_b[t];
}

// ---------------- LSTM step 1 ----------------
__global__ __launch_bounds__(256) void lstm_cell_first(float* __restrict__ hout)
{
    int idx = blockIdx.x * 256 + threadIdx.x;
    int m = idx >> 9, j = idx & 511;
    const float* zr = g_zq + (size_t)m * G4;
    float iv = zr[j], gv = zr[1024 + j], ov = zr[1536 + j];
    float c2 = sigf(iv) * tanhf(gv);   // c_prev = 0
    g_c[idx] = c2;
    if (j < DM) {
        float h2 = sigf(ov) * tanhf(c2);
        hout[m * DM + j] = g_query_g[m * DM + j] + h2;
    }
}

// ---------------- final cosine score ----------------
__global__ __launch_bounds__(256) void final_kernel(const float* __restrict__ h,
                                                    float* __restrict__ out)
{
    int warp = threadIdx.x >> 5, lane = threadIdx.x & 31;
    int m = blockIdx.x * 8 + warp;
    float d = 0.f, hh = 0.f;
#pragma unroll
    for (int jj = 0; jj < 8; jj++) {
        int j = lane + 32 * jj;
        float hv = h[m * DM + j];
        d += hv * g_support_g[j];
        hh += hv * hv;
    }
    d = warp_sum(d); hh = warp_sum(hh);
    if (lane == 0) out[m] = d / (fmaxf(sqrtf(hh), 1e-12f) * g_sg_norm);
}

// ---------------- launch ----------------
extern "C" void kernel_launch(void* const* d_in, const int* in_sizes, int n_in,
                              void* d_out, int out_size)
{
    const float* emb     = (const float*)d_in[0];
    const float* gcn_W   = (const float*)d_in[1];
    const float* gcn_wb  = (const float*)d_in[2];
    const float* gate_W  = (const float*)d_in[3];
    const float* gate_b  = (const float*)d_in[4];
    const float* se_w1   = (const float*)d_in[5];
    const float* se_b1   = (const float*)d_in[6];
    const float* se_w2   = (const float*)d_in[7];
    const float* se_b2   = (const float*)d_in[8];
    const float* ln_g    = (const float*)d_in[9];
    const float* ln_b    = (const float*)d_in[10];
    const float* W_ih    = (const float*)d_in[11];
    const float* W_hh    = (const float*)d_in[12];
    const float* b_ih    = (const float*)d_in[13];
    const float* b_hh    = (const float*)d_in[14];
    const int*   query   = (const int*)d_in[15];
    const int*   support = (const int*)d_in[16];
    const int*   qlc     = (const int*)d_in[17];
    const int*   qrc     = (const int*)d_in[19];
    const int*   slc     = (const int*)d_in[21];
    const int*   src_    = (const int*)d_in[23];
    const int*   knn_tab = (const int*)d_in[25];
    float* out = (float*)d_out;

    float *p_qn, *p_qg, *p_h1, *p_hpre, *p_zq, *p_hA, *p_hB;
    float *p_cm, *p_km, *p_strv, *p_knm, *p_pvw;
    cudaGetSymbolAddress((void**)&p_qn,   g_query_n);
    cudaGetSymbolAddress((void**)&p_qg,   g_query_g);
    cudaGetSymbolAddress((void**)&p_h1,   g_h1);
    cudaGetSymbolAddress((void**)&p_hpre, g_hpre);
    cudaGetSymbolAddress((void**)&p_zq,   g_zq);
    cudaGetSymbolAddress((void**)&p_hA,   g_hA);
    cudaGetSymbolAddress((void**)&p_hB,   g_hB);
    cudaGetSymbolAddress((void**)&p_cm,   g_cm);
    cudaGetSymbolAddress((void**)&p_km,   g_km);
    cudaGetSymbolAddress((void**)&p_strv, g_strv);
    cudaGetSymbolAddress((void**)&p_knm,  g_knm);
    cudaGetSymbolAddress((void**)&p_pvw,  g_pvw);

    static int attr_done = 0;
    if (!attr_done) {
        cudaFuncSetAttribute(tf32_gemm_cp<64, 1>, cudaFuncAttributeMaxDynamicSharedMemorySize, GEMM64_SMEM);
        cudaFuncSetAttribute(tf32_gemm_cp<64, 2>, cudaFuncAttributeMaxDynamicSharedMemorySize, GEMM64_SMEM);
        cudaFuncSetAttribute(tf32_gemm_cp<128, 3>, cudaFuncAttributeMaxDynamicSharedMemorySize, GEMM128_SMEM);
        cudaFuncSetAttribute(tf32_gemm_cp<64, 4>, cudaFuncAttributeMaxDynamicSharedMemorySize, GEMM64_SMEM);
        cudaFuncSetAttribute(tf32_gemm_cp<64, 5>, cudaFuncAttributeMaxDynamicSharedMemorySize, GEMM64_SMEM);
        cudaFuncSetAttribute(lstm_step_fused, cudaFuncAttributeMaxDynamicSharedMemorySize, GEMM64_SMEM);
        attr_done = 1;
    }

    // 0: support-side neighbor select (10 blocks)
    neighbor_sel_kernel<<<2 * BS, 256>>>(emb, query, support, qlc, qrc, slc, src_, knn_tab, 2 * BQ);
    // 1: query-side neighbor select (4096 blocks)
    neighbor_sel_kernel<<<2 * BQ, 256>>>(emb, query, support, qlc, qrc, slc, src_, knn_tab, 0);
    // 2: pad-rel GCN contribution
    pvw_kernel<<<1, 256>>>(emb, gcn_W);

    // 3 (profiled): strv = tanh(cm @ gcn_W^T + wb)  [NRP x 128]
    {
        dim3 gs(EE / 64, NRP / 128);
        tf32_gemm_cp<64, 4><<<gs, 256, GEMM64_SMEM>>>(p_cm, 256, gcn_W, 256, p_strv, NRP, EE, 256, gcn_wb, nullptr, nullptr);
        // 4: knm = tanh(km @ gcn_W[:,128:]^T + pvW + wb)
        tf32_gemm_cp<64, 5><<<gs, 256, GEMM64_SMEM>>>(p_km, EE, gcn_W + EE, 256, p_knm, NRP, EE, EE, gcn_wb, p_pvw, nullptr);
    }
    // 5: gate + blend -> query_n / supp_n
    gate_blend_kernel<<<(NR + 7) / 8, 256>>>(gate_W, gate_b);

    // 6-7: support SE + reduce/whh
    support_row_kernel<<<BS, 256>>>(se_w1, se_b1, se_w2, se_b2, ln_g, ln_b);
    support_reduce_whh_kernel<<<G4 / 8, 256>>>(W_hh);

    // 8-10: query SE
    {
        dim3 g1(HHs / 64, BQ / 128);
        tf32_gemm_cp<64, 1><<<g1, 256, GEMM64_SMEM>>>(p_qn, DM, se_w1, DM, p_h1, BQ, HHs, DM, se_b1, nullptr, nullptr);
        dim3 g2(DM / 64, BQ / 128);
        tf32_gemm_cp<64, 2><<<g2, 256, GEMM64_SMEM>>>(p_h1, HHs, se_w2, HHs, p_hpre, BQ, DM, HHs, se_b2, nullptr, p_qn);
        ln_kernel<<<BQ, 256>>>(ln_g, ln_b);
    }

    // 11: zq
    dim3 g3(G4 / 128, BQ / 128);
    tf32_gemm_cp<128, 3><<<g3, 256, GEMM128_SMEM>>>(p_qg, DM, W_ih, DM, p_zq, BQ, G4, DM, b_ih, b_hh, nullptr);

    // 12: step 1
    lstm_cell_first<<<(BQ * HHs) / 256, 256>>>(p_hA);

    // 13-15: steps 2..4 fused
    dim3 gf(HHs / 16, BQ / 128);
    lstm_step_fused<<<gf, 256, GEMM64_SMEM>>>(p_hA, W_hh, p_hB);
    lstm_step_fused<<<gf, 256, GEMM64_SMEM>>>(p_hB, W_hh, p_hA);
    lstm_step_fused<<<gf, 256, GEMM64_SMEM>>>(p_hA, W_hh, p_hB);

    // 16: cosine score
    final_kernel<<<BQ / 8, 256>>>(p_hB, out);
}